// round 11
// baseline (speedup 1.0000x reference)
#include <cuda_runtime.h>
#include <cuda_bf16.h>

#define D      128
#define GATES  512
#define BATCH  64
#define NVAR   32
#define LSEQ   128
#define BSUB   16
#define PSPLIT 4

#define RES_K   96                       // resident k rows 0..95 in SMEM
#define RES_F   (RES_K * GATES)          // 49152 floats = 192KB
#define RES_B   (RES_F * 4)
#define LDG_K0  96                       // k 96..127 via LDG each step

#define RECON_SZ   260096
#define PRED_OFF   260096
#define CSTAR_OFF  262144

typedef unsigned long long u64;

// ---------------- device scratch ----------------
__device__ __align__(16) float g_WtEnc[NVAR * D * GATES];   // [n][k][g]
__device__ __align__(16) float g_WtDec[NVAR * D * GATES];   // [n][k][g]
__device__ __align__(16) float g_WtIH [NVAR * D * D];       // [n][k][e]
__device__ __align__(16) float g_WtIC [NVAR * D * D];       // [n][k][e]
__device__ __align__(16) float g_WqkvT[D * 384];            // [k][j]
__device__ __align__(16) float g_C    [BATCH * NVAR * D];   // (B,N,D)
__device__ __align__(16) float g_Cstar[BATCH * NVAR * D];   // (B,N,D)

// ---------------- helpers ----------------
__device__ __forceinline__ u64 ffma2(u64 a, u64 b, u64 c) {
    u64 d; asm("fma.rn.f32x2 %0, %1, %2, %3;" : "=l"(d) : "l"(a), "l"(b), "l"(c)); return d;
}
__device__ __forceinline__ u64 pack2(float lo, float hi) {
    u64 r; asm("mov.b64 %0, {%1, %2};" : "=l"(r) : "f"(lo), "f"(hi)); return r;
}
__device__ __forceinline__ void unpack2(u64 v, float& lo, float& hi) {
    asm("mov.b64 {%0, %1}, %2;" : "=f"(lo), "=f"(hi) : "l"(v));
}
__device__ __forceinline__ float fsig(float x)  { return __fdividef(1.f, 1.f + __expf(-x)); }
__device__ __forceinline__ float ftanhf(float x){ return 1.f - __fdividef(2.f, __expf(2.f * x) + 1.f); }

__device__ __forceinline__ unsigned smem_u32(const void* p) {
    return (unsigned)__cvta_generic_to_shared(p);
}
__device__ __forceinline__ void mbar_init(unsigned mbar, unsigned count) {
    asm volatile("mbarrier.init.shared.b64 [%0], %1;" :: "r"(mbar), "r"(count) : "memory");
}
__device__ __forceinline__ void mbar_expect_tx(unsigned mbar, unsigned bytes) {
    asm volatile("mbarrier.arrive.expect_tx.shared.b64 _, [%0], %1;"
                 :: "r"(mbar), "r"(bytes) : "memory");
}
__device__ __forceinline__ void mbar_wait(unsigned mbar, unsigned phase) {
    unsigned done;
    asm volatile(
        "{\n\t.reg .pred p;\n\t"
        "mbarrier.try_wait.parity.acquire.cta.shared::cta.b64 p, [%1], %2;\n\t"
        "selp.b32 %0, 1, 0, p;\n\t}"
        : "=r"(done) : "r"(mbar), "r"(phase) : "memory");
    if (!done) {
        asm volatile(
            "{\n\t.reg .pred P1;\n\t"
            "W_%=:\n\t"
            "mbarrier.try_wait.parity.acquire.cta.shared::cta.b64 P1, [%0], %1, 0x989680;\n\t"
            "@P1 bra.uni DN_%=;\n\t"
            "bra.uni W_%=;\n\t"
            "DN_%=:\n\t}"
            :: "r"(mbar), "r"(phase) : "memory");
    }
}
__device__ __forceinline__ void bulk_copy(const float* gsrc, float* sdst,
                                          unsigned bytes, unsigned mbar) {
    asm volatile(
        "cp.async.bulk.shared::cluster.global.mbarrier::complete_tx::bytes [%0], [%1], %2, [%3];"
        :: "r"(smem_u32(sdst)), "l"(gsrc), "r"(bytes), "r"(mbar) : "memory");
}

struct __align__(16) SmemLSTM {
    float rbuf[RES_F];       // 196608 B resident weights k0..95
    float h2[D][34];         // 17408 B duplicated pairs h2[k][2r]==h2[k][2r+1]
    float sbias[GATES];      // 2048
    float swih[GATES];       // 2048
    float sp[16][16];        // 1024 warp partials
    u64   mbar[2];
};
#define SMEM_BYTES ((int)sizeof(SmemLSTM))

// resident-SMEM chunk of the gate GEMM: lane owns 4 units (u0..u0+3), 4 gate types
__device__ __forceinline__ void gemm_smem(const float* __restrict__ wb,
                                          const float (*h2)[34], int k0, int kc,
                                          int r, int u0, u64 acc[8]) {
    #pragma unroll 8
    for (int kk = 0; kk < kc; kk++) {
        u64 hh = *(const u64*)&h2[k0 + kk][2 * r];
        const float* wrow = wb + kk * GATES + u0;
        #pragma unroll
        for (int t4 = 0; t4 < 4; t4++) {
            ulonglong2 wv = *(const ulonglong2*)(wrow + t4 * 128);
            acc[2 * t4]     = ffma2(wv.x, hh, acc[2 * t4]);
            acc[2 * t4 + 1] = ffma2(wv.y, hh, acc[2 * t4 + 1]);
        }
    }
}
// direct-LDG chunk (weights L2-resident)
__device__ __forceinline__ void gemm_ldg(const float* __restrict__ wg,
                                         const float (*h2)[34], int k0, int kc,
                                         int r, int u0, u64 acc[8]) {
    #pragma unroll 8
    for (int kk = 0; kk < kc; kk++) {
        u64 hh = *(const u64*)&h2[k0 + kk][2 * r];
        const float* wrow = wg + kk * GATES + u0;
        #pragma unroll
        for (int t4 = 0; t4 < 4; t4++) {
            ulonglong2 wv = *(const ulonglong2*)(wrow + t4 * 128);
            acc[2 * t4]     = ffma2(wv.x, hh, acc[2 * t4]);
            acc[2 * t4 + 1] = ffma2(wv.y, hh, acc[2 * t4 + 1]);
        }
    }
}

// ---------------- transpose ----------------
__global__ void transpose_kernel(const float* __restrict__ src, float* __restrict__ dst,
                                 int R, int C) {
    __shared__ float tile[32][33];
    int n = blockIdx.z;
    src += (size_t)n * R * C;
    dst += (size_t)n * R * C;
    int c0 = blockIdx.x * 32, r0 = blockIdx.y * 32;
    #pragma unroll
    for (int i = threadIdx.y; i < 32; i += 8)
        tile[i][threadIdx.x] = src[(r0 + i) * C + c0 + threadIdx.x];
    __syncthreads();
    #pragma unroll
    for (int i = threadIdx.y; i < 32; i += 8)
        dst[(c0 + i) * R + r0 + threadIdx.x] = tile[threadIdx.x][i];
}

// ================= encoder =================
// 512 threads: warp w (0..15) owns units [8w, 8w+8); gh=lane>>4 picks 4-unit half; r=lane&15
__global__ __launch_bounds__(512, 1) void enc_kernel(
    const float* __restrict__ X,
    const float* __restrict__ Wih,
    const float* __restrict__ bih, const float* __restrict__ bhh,
    const float* __restrict__ pool_w, const float* __restrict__ pool_b) {
    extern __shared__ __align__(16) char smraw[];
    SmemLSTM* sm = (SmemLSTM*)smraw;
    const int n = blockIdx.y, p = blockIdx.x;
    const int tid = threadIdx.x, lane = tid & 31, w = tid >> 5;
    const int gh = lane >> 4, r = lane & 15;
    const int u0 = 8 * w + 4 * gh;
    const int b_row = p * BSUB + r;

    for (int i = tid; i < GATES; i += 512) {
        sm->sbias[i] = bih[n * GATES + i] + bhh[n * GATES + i];
        sm->swih[i]  = Wih[n * GATES + i];
    }
    for (int i = tid; i < D * 34; i += 512) ((float*)sm->h2)[i] = 0.f;
    unsigned mbR = smem_u32(&sm->mbar[0]);
    if (tid == 0) mbar_init(mbR, 1);
    __syncthreads();

    const float* Wt = g_WtEnc + (size_t)n * D * GATES;
    const float* Wg = Wt + LDG_K0 * GATES;
    if (tid == 0) {
        mbar_expect_tx(mbR, RES_B);
        bulk_copy(Wt,                 sm->rbuf,             RES_B / 3, mbR);
        bulk_copy(Wt + RES_F / 3,     sm->rbuf + RES_F / 3, RES_B / 3, mbR);
        bulk_copy(Wt + 2 * RES_F / 3, sm->rbuf + 2 * RES_F / 3, RES_B / 3, mbR);
    }

    float c[4], accC[4], hn[4], pw4[4];
    #pragma unroll
    for (int j = 0; j < 4; j++) {
        c[j] = 0.f; accC[j] = 0.f;
        pw4[j] = pool_w[n * D + u0 + j];
    }
    const float pb = pool_b[n];
    float pm = -1e30f, pss = 0.f;   // replicated per lane

    float xcur = X[(b_row * LSEQ + 0) * NVAR + n];
    mbar_wait(mbR, 0);

    for (int t = 0; t < LSEQ - 1; t++) {
        u64 acc[8];
        u64 xx = pack2(xcur, xcur);
        #pragma unroll
        for (int t4 = 0; t4 < 4; t4++) {
            int g0 = t4 * 128 + u0;
            ulonglong2 bv = *(const ulonglong2*)&sm->sbias[g0];
            ulonglong2 wv = *(const ulonglong2*)&sm->swih[g0];
            acc[2 * t4]     = ffma2(wv.x, xx, bv.x);
            acc[2 * t4 + 1] = ffma2(wv.y, xx, bv.y);
        }
        float xnext = X[(b_row * LSEQ + t + 1) * NVAR + n];

        gemm_smem(sm->rbuf, sm->h2, 0, 48, r, u0, acc);                 // k0..47
        gemm_ldg (Wg,       sm->h2, LDG_K0, 32, r, u0, acc);            // k96..127 (L2)
        gemm_smem(sm->rbuf + 48 * GATES, sm->h2, 48, 48, r, u0, acc);   // k48..95

        #pragma unroll
        for (int j = 0; j < 4; j++) {
            float ig, fg, gg, og, d0;
            if (j & 1) { unpack2(acc[0 + (j >> 1)], d0, ig); unpack2(acc[2 + (j >> 1)], d0, fg);
                         unpack2(acc[4 + (j >> 1)], d0, gg); unpack2(acc[6 + (j >> 1)], d0, og); }
            else       { unpack2(acc[0 + (j >> 1)], ig, d0); unpack2(acc[2 + (j >> 1)], fg, d0);
                         unpack2(acc[4 + (j >> 1)], gg, d0); unpack2(acc[6 + (j >> 1)], og, d0); }
            c[j]  = fsig(fg) * c[j] + fsig(ig) * ftanhf(gg);
            hn[j] = fsig(og) * ftanhf(c[j]);
        }

        float part = hn[0] * pw4[0] + hn[1] * pw4[1] + hn[2] * pw4[2] + hn[3] * pw4[3];
        part += __shfl_xor_sync(0xffffffffu, part, 16);
        __syncthreads();                       // all h2 reads of this step done
        #pragma unroll
        for (int j = 0; j < 4; j++)
            *(u64*)&sm->h2[u0 + j][2 * r] = pack2(hn[j], hn[j]);
        if (gh == 0) sm->sp[w][r] = part;
        __syncthreads();                       // h2 + sp visible

        float s = pb;
        #pragma unroll
        for (int ww = 0; ww < 16; ww++) s += sm->sp[ww][r];
        float mn = fmaxf(pm, s);
        float scale = __expf(pm - mn);
        float wcur  = __expf(s - mn);
        pss = pss * scale + wcur;
        pm = mn;
        #pragma unroll
        for (int j = 0; j < 4; j++) accC[j] = accC[j] * scale + wcur * hn[j];
        xcur = xnext;
    }
    float iv = __fdividef(1.f, pss);
    #pragma unroll
    for (int j = 0; j < 4; j++)
        g_C[(b_row * NVAR + n) * D + u0 + j] = accC[j] * iv;
}

// ================= MHSA =================
__global__ __launch_bounds__(128, 1) void mhsa_kernel(
    const float* __restrict__ bqkv,
    const float* __restrict__ Wo, const float* __restrict__ bo,
    float* __restrict__ out) {
    extern __shared__ __align__(16) float smf[];
    float* Cs  = smf;            // [128][34]
    float* QKV = smf + 4352;     // [32][385]
    float* As  = smf;            // [32][129] reuse
    const int b = blockIdx.x, tid = threadIdx.x;

    #pragma unroll 4
    for (int i = 0; i < 32; i++)
        Cs[tid * 34 + i] = g_C[(b * NVAR + i) * D + tid];
    __syncthreads();

    for (int jj = 0; jj < 3; jj++) {
        int j = jj * 128 + tid;
        float bj = bqkv[j];
        u64 acc[16];
        #pragma unroll
        for (int vp = 0; vp < 16; vp++) acc[vp] = pack2(bj, bj);
        #pragma unroll 2
        for (int k = 0; k < D; k++) {
            float wv = g_WqkvT[k * 384 + j];
            u64 ww = pack2(wv, wv);
            const u64* crow = (const u64*)&Cs[k * 34];
            #pragma unroll
            for (int vp = 0; vp < 16; vp++) acc[vp] = ffma2(ww, crow[vp], acc[vp]);
        }
        #pragma unroll
        for (int vp = 0; vp < 16; vp++) {
            float a0, a1; unpack2(acc[vp], a0, a1);
            QKV[(2 * vp)     * 385 + j] = a0;
            QKV[(2 * vp + 1) * 385 + j] = a1;
        }
    }
    __syncthreads();

    {
        int h = tid >> 5, i = tid & 31;
        float q[32];
        #pragma unroll
        for (int d = 0; d < 32; d++) q[d] = QKV[i * 385 + h * 32 + d];
        float s[32];
        #pragma unroll
        for (int j = 0; j < 32; j++) {
            float a = 0.f;
            #pragma unroll
            for (int d = 0; d < 32; d++) a += q[d] * QKV[j * 385 + 128 + h * 32 + d];
            s[j] = a * 0.17677669529663687f;
        }
        float mx = s[0];
        #pragma unroll
        for (int j = 1; j < 32; j++) mx = fmaxf(mx, s[j]);
        float sum = 0.f;
        #pragma unroll
        for (int j = 0; j < 32; j++) { s[j] = __expf(s[j] - mx); sum += s[j]; }
        float inv = __fdividef(1.f, sum);
        float A[32];
        #pragma unroll
        for (int d = 0; d < 32; d++) A[d] = 0.f;
        #pragma unroll
        for (int j = 0; j < 32; j++) {
            float aj = s[j] * inv;
            #pragma unroll
            for (int d = 0; d < 32; d++) A[d] += aj * QKV[j * 385 + 256 + h * 32 + d];
        }
        #pragma unroll
        for (int d = 0; d < 32; d++) As[i * 129 + h * 32 + d] = A[d];
    }
    __syncthreads();

    {
        int v = tid & 31, uc = tid >> 5;
        for (int mm = 0; mm < 32; mm++) {
            int u = uc * 32 + mm;
            float a = bo[u];
            #pragma unroll 4
            for (int d = 0; d < D; d++) a += As[v * 129 + d] * Wo[u * D + d];
            g_Cstar[(b * NVAR + v) * D + u] = a;
            out[CSTAR_OFF + (b * NVAR + v) * D + u] = a;
        }
    }
}

// ================= decoder =================
__global__ __launch_bounds__(512, 1) void dec_kernel(
    const float* __restrict__ ih_b, const float* __restrict__ ic_b,
    const float* __restrict__ bih,  const float* __restrict__ bhh,
    const float* __restrict__ out_w, const float* __restrict__ out_b,
    float* __restrict__ out) {
    extern __shared__ __align__(16) char smraw[];
    SmemLSTM* sm = (SmemLSTM*)smraw;
    const int n = blockIdx.y, p = blockIdx.x;
    const int tid = threadIdx.x, lane = tid & 31, w = tid >> 5;
    const int gh = lane >> 4, r = lane & 15;
    const int u0 = 8 * w + 4 * gh;
    const int b_row = p * BSUB + r;

    for (int i = tid; i < GATES; i += 512)
        sm->sbias[i] = bih[n * GATES + i] + bhh[n * GATES + i];
    #pragma unroll
    for (int i = 0; i < 4; i++) {
        int idx = i * 512 + tid;
        int rr = idx >> 7, k = idx & 127;
        float v = g_Cstar[((p * BSUB + rr) * NVAR + n) * D + k];
        sm->h2[k][2 * rr] = v; sm->h2[k][2 * rr + 1] = v;
    }
    unsigned mbR = smem_u32(&sm->mbar[0]);
    if (tid == 0) mbar_init(mbR, 1);
    __syncthreads();

    const float* Wt = g_WtDec + (size_t)n * D * GATES;
    const float* Wg = Wt + LDG_K0 * GATES;
    if (tid == 0) {
        mbar_expect_tx(mbR, RES_B);
        bulk_copy(Wt,                 sm->rbuf,                 RES_B / 3, mbR);
        bulk_copy(Wt + RES_F / 3,     sm->rbuf + RES_F / 3,     RES_B / 3, mbR);
        bulk_copy(Wt + 2 * RES_F / 3, sm->rbuf + 2 * RES_F / 3, RES_B / 3, mbR);
    }

    // init matvecs from LDG weights (one-time, overlaps bulk copy)
    const float* WtIH = g_WtIH + (size_t)n * D * D;
    const float* WtIC = g_WtIC + (size_t)n * D * D;
    u64 ah[2], ac2[2];
    ah[0]  = pack2(ih_b[n * D + u0],     ih_b[n * D + u0 + 1]);
    ah[1]  = pack2(ih_b[n * D + u0 + 2], ih_b[n * D + u0 + 3]);
    ac2[0] = pack2(ic_b[n * D + u0],     ic_b[n * D + u0 + 1]);
    ac2[1] = pack2(ic_b[n * D + u0 + 2], ic_b[n * D + u0 + 3]);
    #pragma unroll 4
    for (int k = 0; k < D; k++) {
        u64 hh = *(const u64*)&sm->h2[k][2 * r];
        ulonglong2 wh = *(const ulonglong2*)(WtIH + k * D + u0);
        ulonglong2 wc = *(const ulonglong2*)(WtIC + k * D + u0);
        ah[0]  = ffma2(wh.x, hh, ah[0]);  ah[1]  = ffma2(wh.y, hh, ah[1]);
        ac2[0] = ffma2(wc.x, hh, ac2[0]); ac2[1] = ffma2(wc.y, hh, ac2[1]);
    }
    float hn[4], c[4], wout4[4];
    {
        float a0, a1;
        unpack2(ah[0], a0, a1);  hn[0] = ftanhf(a0); hn[1] = ftanhf(a1);
        unpack2(ah[1], a0, a1);  hn[2] = ftanhf(a0); hn[3] = ftanhf(a1);
        unpack2(ac2[0], a0, a1); c[0] = ftanhf(a0);  c[1] = ftanhf(a1);
        unpack2(ac2[1], a0, a1); c[2] = ftanhf(a0);  c[3] = ftanhf(a1);
    }
    #pragma unroll
    for (int j = 0; j < 4; j++) wout4[j] = out_w[n * D + u0 + j];
    const float ob = out_b[n];

    __syncthreads();                 // everyone done reading staged C_star from h2
    #pragma unroll
    for (int j = 0; j < 4; j++)
        *(u64*)&sm->h2[u0 + j][2 * r] = pack2(hn[j], hn[j]);
    __syncthreads();

    mbar_wait(mbR, 0);

    for (int l = 0; l < LSEQ; l++) {
        u64 acc[8];
        #pragma unroll
        for (int t4 = 0; t4 < 4; t4++) {
            ulonglong2 bv = *(const ulonglong2*)&sm->sbias[t4 * 128 + u0];
            acc[2 * t4] = bv.x; acc[2 * t4 + 1] = bv.y;
        }

        gemm_smem(sm->rbuf, sm->h2, 0, 48, r, u0, acc);
        gemm_ldg (Wg,       sm->h2, LDG_K0, 32, r, u0, acc);
        gemm_smem(sm->rbuf + 48 * GATES, sm->h2, 48, 48, r, u0, acc);

        #pragma unroll
        for (int j = 0; j < 4; j++) {
            float ig, fg, gg, og, d0;
            if (j & 1) { unpack2(acc[0 + (j >> 1)], d0, ig); unpack2(acc[2 + (j >> 1)], d0, fg);
                         unpack2(acc[4 + (j >> 1)], d0, gg); unpack2(acc[6 + (j >> 1)], d0, og); }
            else       { unpack2(acc[0 + (j >> 1)], ig, d0); unpack2(acc[2 + (j >> 1)], fg, d0);
                         unpack2(acc[4 + (j >> 1)], gg, d0); unpack2(acc[6 + (j >> 1)], og, d0); }
            c[j]  = fsig(fg) * c[j] + fsig(ig) * ftanhf(gg);
            hn[j] = fsig(og) * ftanhf(c[j]);
        }

        float part = hn[0] * wout4[0] + hn[1] * wout4[1] + hn[2] * wout4[2] + hn[3] * wout4[3];
        part += __shfl_xor_sync(0xffffffffu, part, 16);
        __syncthreads();
        #pragma unroll
        for (int j = 0; j < 4; j++)
            *(u64*)&sm->h2[u0 + j][2 * r] = pack2(hn[j], hn[j]);
        if (gh == 0) sm->sp[w][r] = part;
        __syncthreads();

        if (w == 0 && gh == 0) {
            float O = ob;
            #pragma unroll
            for (int ww = 0; ww < 16; ww++) O += sm->sp[ww][r];
            if (l < LSEQ - 1) out[(b_row * (LSEQ - 1) + l) * NVAR + n] = O;
            else              out[PRED_OFF + b_row * NVAR + n] = O;
        }
    }
}

// ---------------- launch ----------------
extern "C" void kernel_launch(void* const* d_in, const int* in_sizes, int n_in,
                              void* d_out, int out_size) {
    (void)in_sizes; (void)n_in; (void)out_size;
    const float* X        = (const float*)d_in[0];
    const float* enc_Wih  = (const float*)d_in[1];
    const float* enc_Whh  = (const float*)d_in[2];
    const float* enc_bih  = (const float*)d_in[3];
    const float* enc_bhh  = (const float*)d_in[4];
    const float* pool_w   = (const float*)d_in[5];
    const float* pool_b   = (const float*)d_in[6];
    const float* Wqkv     = (const float*)d_in[7];
    const float* bqkv     = (const float*)d_in[8];
    const float* Wo       = (const float*)d_in[9];
    const float* bo       = (const float*)d_in[10];
    const float* dec_ih_W = (const float*)d_in[11];
    const float* dec_ih_b = (const float*)d_in[12];
    const float* dec_ic_W = (const float*)d_in[13];
    const float* dec_ic_b = (const float*)d_in[14];
    const float* dec_Whh  = (const float*)d_in[16];
    const float* dec_bih  = (const float*)d_in[17];
    const float* dec_bhh  = (const float*)d_in[18];
    const float* dec_out_W= (const float*)d_in[19];
    const float* dec_out_b= (const float*)d_in[20];
    float* out = (float*)d_out;

    static int attr_set = 0;
    if (!attr_set) {
        cudaFuncSetAttribute(mhsa_kernel, cudaFuncAttributeMaxDynamicSharedMemorySize, 66688);
        cudaFuncSetAttribute(enc_kernel,  cudaFuncAttributeMaxDynamicSharedMemorySize, SMEM_BYTES);
        cudaFuncSetAttribute(dec_kernel,  cudaFuncAttributeMaxDynamicSharedMemorySize, SMEM_BYTES);
        attr_set = 1;
    }

    float *pWtEnc, *pWtDec, *pWtIH, *pWtIC, *pWqkvT;
    cudaGetSymbolAddress((void**)&pWtEnc, g_WtEnc);
    cudaGetSymbolAddress((void**)&pWtDec, g_WtDec);
    cudaGetSymbolAddress((void**)&pWtIH,  g_WtIH);
    cudaGetSymbolAddress((void**)&pWtIC,  g_WtIC);
    cudaGetSymbolAddress((void**)&pWqkvT, g_WqkvT);

    dim3 tb(32, 8);
    transpose_kernel<<<dim3(4, 16, 32), tb>>>(enc_Whh,  pWtEnc, 512, 128);
    transpose_kernel<<<dim3(4, 16, 32), tb>>>(dec_Whh,  pWtDec, 512, 128);
    transpose_kernel<<<dim3(4,  4, 32), tb>>>(dec_ih_W, pWtIH,  128, 128);
    transpose_kernel<<<dim3(4,  4, 32), tb>>>(dec_ic_W, pWtIC,  128, 128);
    transpose_kernel<<<dim3(4, 12,  1), tb>>>(Wqkv,     pWqkvT, 384, 128);

    enc_kernel<<<dim3(PSPLIT, NVAR), 512, SMEM_BYTES>>>(X, enc_Wih, enc_bih, enc_bhh,
                                                        pool_w, pool_b);
    mhsa_kernel<<<BATCH, 128, 66688>>>(bqkv, Wo, bo, out);
    dec_kernel<<<dim3(PSPLIT, NVAR), 512, SMEM_BYTES>>>(dec_ih_b, dec_ic_b, dec_bih, dec_bhh,
                                                        dec_out_W, dec_out_b, out);
}

// round 12
// speedup vs baseline: 1.0008x; 1.0008x over previous
#include <cuda_runtime.h>
#include <cuda_bf16.h>

#define D      128
#define GATES  512
#define BATCH  64
#define NVAR   32
#define LSEQ   128
#define BSUB   16
#define PSPLIT 4

#define RES_K   96                       // resident k rows 0..95 in SMEM
#define RES_F   (RES_K * GATES)          // 49152 floats = 192KB
#define RES_B   (RES_F * 4)
#define LDG_K0  96                       // k 96..127 via LDG each step

#define RECON_SZ   260096
#define PRED_OFF   260096
#define CSTAR_OFF  262144

typedef unsigned long long u64;

// ---------------- device scratch ----------------
__device__ __align__(16) float g_WtEnc[NVAR * D * GATES];   // [n][k][g]
__device__ __align__(16) float g_WtDec[NVAR * D * GATES];   // [n][k][g]
__device__ __align__(16) float g_WtIH [NVAR * D * D];       // [n][k][e]
__device__ __align__(16) float g_WtIC [NVAR * D * D];       // [n][k][e]
__device__ __align__(16) float g_WqkvT[D * 384];            // [k][j]
__device__ __align__(16) float g_C    [BATCH * NVAR * D];   // (B,N,D)
__device__ __align__(16) float g_Cstar[BATCH * NVAR * D];   // (B,N,D)

// ---------------- helpers ----------------
__device__ __forceinline__ u64 ffma2(u64 a, u64 b, u64 c) {
    u64 d; asm("fma.rn.f32x2 %0, %1, %2, %3;" : "=l"(d) : "l"(a), "l"(b), "l"(c)); return d;
}
__device__ __forceinline__ u64 pack2(float lo, float hi) {
    u64 r; asm("mov.b64 %0, {%1, %2};" : "=l"(r) : "f"(lo), "f"(hi)); return r;
}
__device__ __forceinline__ void unpack2(u64 v, float& lo, float& hi) {
    asm("mov.b64 {%0, %1}, %2;" : "=f"(lo), "=f"(hi) : "l"(v));
}
__device__ __forceinline__ float fsig(float x)  { return __fdividef(1.f, 1.f + __expf(-x)); }
__device__ __forceinline__ float ftanhf(float x){ return 1.f - __fdividef(2.f, __expf(2.f * x) + 1.f); }

__device__ __forceinline__ unsigned smem_u32(const void* p) {
    return (unsigned)__cvta_generic_to_shared(p);
}
__device__ __forceinline__ void mbar_init(unsigned mbar, unsigned count) {
    asm volatile("mbarrier.init.shared.b64 [%0], %1;" :: "r"(mbar), "r"(count) : "memory");
}
__device__ __forceinline__ void mbar_expect_tx(unsigned mbar, unsigned bytes) {
    asm volatile("mbarrier.arrive.expect_tx.shared.b64 _, [%0], %1;"
                 :: "r"(mbar), "r"(bytes) : "memory");
}
__device__ __forceinline__ void mbar_wait(unsigned mbar, unsigned phase) {
    unsigned done;
    asm volatile(
        "{\n\t.reg .pred p;\n\t"
        "mbarrier.try_wait.parity.acquire.cta.shared::cta.b64 p, [%1], %2;\n\t"
        "selp.b32 %0, 1, 0, p;\n\t}"
        : "=r"(done) : "r"(mbar), "r"(phase) : "memory");
    if (!done) {
        asm volatile(
            "{\n\t.reg .pred P1;\n\t"
            "W_%=:\n\t"
            "mbarrier.try_wait.parity.acquire.cta.shared::cta.b64 P1, [%0], %1, 0x989680;\n\t"
            "@P1 bra.uni DN_%=;\n\t"
            "bra.uni W_%=;\n\t"
            "DN_%=:\n\t}"
            :: "r"(mbar), "r"(phase) : "memory");
    }
}
__device__ __forceinline__ void bulk_copy(const float* gsrc, float* sdst,
                                          unsigned bytes, unsigned mbar) {
    asm volatile(
        "cp.async.bulk.shared::cluster.global.mbarrier::complete_tx::bytes [%0], [%1], %2, [%3];"
        :: "r"(smem_u32(sdst)), "l"(gsrc), "r"(bytes), "r"(mbar) : "memory");
}

struct __align__(16) SmemLSTM {
    float rbuf[RES_F];       // 196608 B resident weights k0..95
    float h2[D][34];         // 17408 B duplicated pairs h2[k][2r]==h2[k][2r+1]
    float sbias[GATES];      // 2048
    float swih[GATES];       // 2048
    float sp[16][16];        // 1024 warp partials
    u64   mbar[2];
};
#define SMEM_BYTES ((int)sizeof(SmemLSTM))

// resident-SMEM chunk of the gate GEMM: lane owns 4 units (u0..u0+3), 4 gate types
__device__ __forceinline__ void gemm_smem(const float* __restrict__ wb,
                                          const float (*h2)[34], int k0, int kc,
                                          int r, int u0, u64 acc[8]) {
    #pragma unroll 8
    for (int kk = 0; kk < kc; kk++) {
        u64 hh = *(const u64*)&h2[k0 + kk][2 * r];
        const float* wrow = wb + kk * GATES + u0;
        #pragma unroll
        for (int t4 = 0; t4 < 4; t4++) {
            ulonglong2 wv = *(const ulonglong2*)(wrow + t4 * 128);
            acc[2 * t4]     = ffma2(wv.x, hh, acc[2 * t4]);
            acc[2 * t4 + 1] = ffma2(wv.y, hh, acc[2 * t4 + 1]);
        }
    }
}
// direct-LDG chunk (weights L2-resident)
__device__ __forceinline__ void gemm_ldg(const float* __restrict__ wg,
                                         const float (*h2)[34], int k0, int kc,
                                         int r, int u0, u64 acc[8]) {
    #pragma unroll 8
    for (int kk = 0; kk < kc; kk++) {
        u64 hh = *(const u64*)&h2[k0 + kk][2 * r];
        const float* wrow = wg + kk * GATES + u0;
        #pragma unroll
        for (int t4 = 0; t4 < 4; t4++) {
            ulonglong2 wv = *(const ulonglong2*)(wrow + t4 * 128);
            acc[2 * t4]     = ffma2(wv.x, hh, acc[2 * t4]);
            acc[2 * t4 + 1] = ffma2(wv.y, hh, acc[2 * t4 + 1]);
        }
    }
}

// ---------------- transpose ----------------
__global__ void transpose_kernel(const float* __restrict__ src, float* __restrict__ dst,
                                 int R, int C) {
    __shared__ float tile[32][33];
    int n = blockIdx.z;
    src += (size_t)n * R * C;
    dst += (size_t)n * R * C;
    int c0 = blockIdx.x * 32, r0 = blockIdx.y * 32;
    #pragma unroll
    for (int i = threadIdx.y; i < 32; i += 8)
        tile[i][threadIdx.x] = src[(r0 + i) * C + c0 + threadIdx.x];
    __syncthreads();
    #pragma unroll
    for (int i = threadIdx.y; i < 32; i += 8)
        dst[(c0 + i) * R + r0 + threadIdx.x] = tile[threadIdx.x][i];
}

// ================= encoder =================
// 512 threads: warp w (0..15) owns units [8w, 8w+8); gh=lane>>4 picks 4-unit half; r=lane&15
__global__ __launch_bounds__(512, 1) void enc_kernel(
    const float* __restrict__ X,
    const float* __restrict__ Wih,
    const float* __restrict__ bih, const float* __restrict__ bhh,
    const float* __restrict__ pool_w, const float* __restrict__ pool_b) {
    extern __shared__ __align__(16) char smraw[];
    SmemLSTM* sm = (SmemLSTM*)smraw;
    const int n = blockIdx.y, p = blockIdx.x;
    const int tid = threadIdx.x, lane = tid & 31, w = tid >> 5;
    const int gh = lane >> 4, r = lane & 15;
    const int u0 = 8 * w + 4 * gh;
    const int b_row = p * BSUB + r;

    for (int i = tid; i < GATES; i += 512) {
        sm->sbias[i] = bih[n * GATES + i] + bhh[n * GATES + i];
        sm->swih[i]  = Wih[n * GATES + i];
    }
    for (int i = tid; i < D * 34; i += 512) ((float*)sm->h2)[i] = 0.f;
    unsigned mbR = smem_u32(&sm->mbar[0]);
    if (tid == 0) mbar_init(mbR, 1);
    __syncthreads();

    const float* Wt = g_WtEnc + (size_t)n * D * GATES;
    const float* Wg = Wt + LDG_K0 * GATES;
    if (tid == 0) {
        mbar_expect_tx(mbR, RES_B);
        bulk_copy(Wt,                 sm->rbuf,             RES_B / 3, mbR);
        bulk_copy(Wt + RES_F / 3,     sm->rbuf + RES_F / 3, RES_B / 3, mbR);
        bulk_copy(Wt + 2 * RES_F / 3, sm->rbuf + 2 * RES_F / 3, RES_B / 3, mbR);
    }

    float c[4], accC[4], hn[4], pw4[4];
    #pragma unroll
    for (int j = 0; j < 4; j++) {
        c[j] = 0.f; accC[j] = 0.f;
        pw4[j] = pool_w[n * D + u0 + j];
    }
    const float pb = pool_b[n];
    float pm = -1e30f, pss = 0.f;   // replicated per lane

    float xcur = X[(b_row * LSEQ + 0) * NVAR + n];
    mbar_wait(mbR, 0);

    for (int t = 0; t < LSEQ - 1; t++) {
        u64 acc[8];
        u64 xx = pack2(xcur, xcur);
        #pragma unroll
        for (int t4 = 0; t4 < 4; t4++) {
            int g0 = t4 * 128 + u0;
            ulonglong2 bv = *(const ulonglong2*)&sm->sbias[g0];
            ulonglong2 wv = *(const ulonglong2*)&sm->swih[g0];
            acc[2 * t4]     = ffma2(wv.x, xx, bv.x);
            acc[2 * t4 + 1] = ffma2(wv.y, xx, bv.y);
        }
        float xnext = X[(b_row * LSEQ + t + 1) * NVAR + n];

        gemm_smem(sm->rbuf, sm->h2, 0, 48, r, u0, acc);                 // k0..47
        gemm_ldg (Wg,       sm->h2, LDG_K0, 32, r, u0, acc);            // k96..127 (L2)
        gemm_smem(sm->rbuf + 48 * GATES, sm->h2, 48, 48, r, u0, acc);   // k48..95

        #pragma unroll
        for (int j = 0; j < 4; j++) {
            float ig, fg, gg, og, d0;
            if (j & 1) { unpack2(acc[0 + (j >> 1)], d0, ig); unpack2(acc[2 + (j >> 1)], d0, fg);
                         unpack2(acc[4 + (j >> 1)], d0, gg); unpack2(acc[6 + (j >> 1)], d0, og); }
            else       { unpack2(acc[0 + (j >> 1)], ig, d0); unpack2(acc[2 + (j >> 1)], fg, d0);
                         unpack2(acc[4 + (j >> 1)], gg, d0); unpack2(acc[6 + (j >> 1)], og, d0); }
            c[j]  = fsig(fg) * c[j] + fsig(ig) * ftanhf(gg);
            hn[j] = fsig(og) * ftanhf(c[j]);
        }

        float part = hn[0] * pw4[0] + hn[1] * pw4[1] + hn[2] * pw4[2] + hn[3] * pw4[3];
        part += __shfl_xor_sync(0xffffffffu, part, 16);
        __syncthreads();                       // all h2 reads of this step done
        #pragma unroll
        for (int j = 0; j < 4; j++)
            *(u64*)&sm->h2[u0 + j][2 * r] = pack2(hn[j], hn[j]);
        if (gh == 0) sm->sp[w][r] = part;
        __syncthreads();                       // h2 + sp visible

        float s = pb;
        #pragma unroll
        for (int ww = 0; ww < 16; ww++) s += sm->sp[ww][r];
        float mn = fmaxf(pm, s);
        float scale = __expf(pm - mn);
        float wcur  = __expf(s - mn);
        pss = pss * scale + wcur;
        pm = mn;
        #pragma unroll
        for (int j = 0; j < 4; j++) accC[j] = accC[j] * scale + wcur * hn[j];
        xcur = xnext;
    }
    float iv = __fdividef(1.f, pss);
    #pragma unroll
    for (int j = 0; j < 4; j++)
        g_C[(b_row * NVAR + n) * D + u0 + j] = accC[j] * iv;
}

// ================= MHSA =================
__global__ __launch_bounds__(128, 1) void mhsa_kernel(
    const float* __restrict__ bqkv,
    const float* __restrict__ Wo, const float* __restrict__ bo,
    float* __restrict__ out) {
    extern __shared__ __align__(16) float smf[];
    float* Cs  = smf;            // [128][34]
    float* QKV = smf + 4352;     // [32][385]
    float* As  = smf;            // [32][129] reuse
    const int b = blockIdx.x, tid = threadIdx.x;

    #pragma unroll 4
    for (int i = 0; i < 32; i++)
        Cs[tid * 34 + i] = g_C[(b * NVAR + i) * D + tid];
    __syncthreads();

    for (int jj = 0; jj < 3; jj++) {
        int j = jj * 128 + tid;
        float bj = bqkv[j];
        u64 acc[16];
        #pragma unroll
        for (int vp = 0; vp < 16; vp++) acc[vp] = pack2(bj, bj);
        #pragma unroll 2
        for (int k = 0; k < D; k++) {
            float wv = g_WqkvT[k * 384 + j];
            u64 ww = pack2(wv, wv);
            const u64* crow = (const u64*)&Cs[k * 34];
            #pragma unroll
            for (int vp = 0; vp < 16; vp++) acc[vp] = ffma2(ww, crow[vp], acc[vp]);
        }
        #pragma unroll
        for (int vp = 0; vp < 16; vp++) {
            float a0, a1; unpack2(acc[vp], a0, a1);
            QKV[(2 * vp)     * 385 + j] = a0;
            QKV[(2 * vp + 1) * 385 + j] = a1;
        }
    }
    __syncthreads();

    {
        int h = tid >> 5, i = tid & 31;
        float q[32];
        #pragma unroll
        for (int d = 0; d < 32; d++) q[d] = QKV[i * 385 + h * 32 + d];
        float s[32];
        #pragma unroll
        for (int j = 0; j < 32; j++) {
            float a = 0.f;
            #pragma unroll
            for (int d = 0; d < 32; d++) a += q[d] * QKV[j * 385 + 128 + h * 32 + d];
            s[j] = a * 0.17677669529663687f;
        }
        float mx = s[0];
        #pragma unroll
        for (int j = 1; j < 32; j++) mx = fmaxf(mx, s[j]);
        float sum = 0.f;
        #pragma unroll
        for (int j = 0; j < 32; j++) { s[j] = __expf(s[j] - mx); sum += s[j]; }
        float inv = __fdividef(1.f, sum);
        float A[32];
        #pragma unroll
        for (int d = 0; d < 32; d++) A[d] = 0.f;
        #pragma unroll
        for (int j = 0; j < 32; j++) {
            float aj = s[j] * inv;
            #pragma unroll
            for (int d = 0; d < 32; d++) A[d] += aj * QKV[j * 385 + 256 + h * 32 + d];
        }
        #pragma unroll
        for (int d = 0; d < 32; d++) As[i * 129 + h * 32 + d] = A[d];
    }
    __syncthreads();

    {
        int v = tid & 31, uc = tid >> 5;
        for (int mm = 0; mm < 32; mm++) {
            int u = uc * 32 + mm;
            float a = bo[u];
            #pragma unroll 4
            for (int d = 0; d < D; d++) a += As[v * 129 + d] * Wo[u * D + d];
            g_Cstar[(b * NVAR + v) * D + u] = a;
            out[CSTAR_OFF + (b * NVAR + v) * D + u] = a;
        }
    }
}

// ================= decoder =================
__global__ __launch_bounds__(512, 1) void dec_kernel(
    const float* __restrict__ ih_b, const float* __restrict__ ic_b,
    const float* __restrict__ bih,  const float* __restrict__ bhh,
    const float* __restrict__ out_w, const float* __restrict__ out_b,
    float* __restrict__ out) {
    extern __shared__ __align__(16) char smraw[];
    SmemLSTM* sm = (SmemLSTM*)smraw;
    const int n = blockIdx.y, p = blockIdx.x;
    const int tid = threadIdx.x, lane = tid & 31, w = tid >> 5;
    const int gh = lane >> 4, r = lane & 15;
    const int u0 = 8 * w + 4 * gh;
    const int b_row = p * BSUB + r;

    for (int i = tid; i < GATES; i += 512)
        sm->sbias[i] = bih[n * GATES + i] + bhh[n * GATES + i];
    #pragma unroll
    for (int i = 0; i < 4; i++) {
        int idx = i * 512 + tid;
        int rr = idx >> 7, k = idx & 127;
        float v = g_Cstar[((p * BSUB + rr) * NVAR + n) * D + k];
        sm->h2[k][2 * rr] = v; sm->h2[k][2 * rr + 1] = v;
    }
    unsigned mbR = smem_u32(&sm->mbar[0]);
    if (tid == 0) mbar_init(mbR, 1);
    __syncthreads();

    const float* Wt = g_WtDec + (size_t)n * D * GATES;
    const float* Wg = Wt + LDG_K0 * GATES;
    if (tid == 0) {
        mbar_expect_tx(mbR, RES_B);
        bulk_copy(Wt,                 sm->rbuf,                 RES_B / 3, mbR);
        bulk_copy(Wt + RES_F / 3,     sm->rbuf + RES_F / 3,     RES_B / 3, mbR);
        bulk_copy(Wt + 2 * RES_F / 3, sm->rbuf + 2 * RES_F / 3, RES_B / 3, mbR);
    }

    // init matvecs from LDG weights (one-time, overlaps bulk copy)
    const float* WtIH = g_WtIH + (size_t)n * D * D;
    const float* WtIC = g_WtIC + (size_t)n * D * D;
    u64 ah[2], ac2[2];
    ah[0]  = pack2(ih_b[n * D + u0],     ih_b[n * D + u0 + 1]);
    ah[1]  = pack2(ih_b[n * D + u0 + 2], ih_b[n * D + u0 + 3]);
    ac2[0] = pack2(ic_b[n * D + u0],     ic_b[n * D + u0 + 1]);
    ac2[1] = pack2(ic_b[n * D + u0 + 2], ic_b[n * D + u0 + 3]);
    #pragma unroll 4
    for (int k = 0; k < D; k++) {
        u64 hh = *(const u64*)&sm->h2[k][2 * r];
        ulonglong2 wh = *(const ulonglong2*)(WtIH + k * D + u0);
        ulonglong2 wc = *(const ulonglong2*)(WtIC + k * D + u0);
        ah[0]  = ffma2(wh.x, hh, ah[0]);  ah[1]  = ffma2(wh.y, hh, ah[1]);
        ac2[0] = ffma2(wc.x, hh, ac2[0]); ac2[1] = ffma2(wc.y, hh, ac2[1]);
    }
    float hn[4], c[4], wout4[4];
    {
        float a0, a1;
        unpack2(ah[0], a0, a1);  hn[0] = ftanhf(a0); hn[1] = ftanhf(a1);
        unpack2(ah[1], a0, a1);  hn[2] = ftanhf(a0); hn[3] = ftanhf(a1);
        unpack2(ac2[0], a0, a1); c[0] = ftanhf(a0);  c[1] = ftanhf(a1);
        unpack2(ac2[1], a0, a1); c[2] = ftanhf(a0);  c[3] = ftanhf(a1);
    }
    #pragma unroll
    for (int j = 0; j < 4; j++) wout4[j] = out_w[n * D + u0 + j];
    const float ob = out_b[n];

    __syncthreads();                 // everyone done reading staged C_star from h2
    #pragma unroll
    for (int j = 0; j < 4; j++)
        *(u64*)&sm->h2[u0 + j][2 * r] = pack2(hn[j], hn[j]);
    __syncthreads();

    mbar_wait(mbR, 0);

    for (int l = 0; l < LSEQ; l++) {
        u64 acc[8];
        #pragma unroll
        for (int t4 = 0; t4 < 4; t4++) {
            ulonglong2 bv = *(const ulonglong2*)&sm->sbias[t4 * 128 + u0];
            acc[2 * t4] = bv.x; acc[2 * t4 + 1] = bv.y;
        }

        gemm_smem(sm->rbuf, sm->h2, 0, 48, r, u0, acc);
        gemm_ldg (Wg,       sm->h2, LDG_K0, 32, r, u0, acc);
        gemm_smem(sm->rbuf + 48 * GATES, sm->h2, 48, 48, r, u0, acc);

        #pragma unroll
        for (int j = 0; j < 4; j++) {
            float ig, fg, gg, og, d0;
            if (j & 1) { unpack2(acc[0 + (j >> 1)], d0, ig); unpack2(acc[2 + (j >> 1)], d0, fg);
                         unpack2(acc[4 + (j >> 1)], d0, gg); unpack2(acc[6 + (j >> 1)], d0, og); }
            else       { unpack2(acc[0 + (j >> 1)], ig, d0); unpack2(acc[2 + (j >> 1)], fg, d0);
                         unpack2(acc[4 + (j >> 1)], gg, d0); unpack2(acc[6 + (j >> 1)], og, d0); }
            c[j]  = fsig(fg) * c[j] + fsig(ig) * ftanhf(gg);
            hn[j] = fsig(og) * ftanhf(c[j]);
        }

        float part = hn[0] * wout4[0] + hn[1] * wout4[1] + hn[2] * wout4[2] + hn[3] * wout4[3];
        part += __shfl_xor_sync(0xffffffffu, part, 16);
        __syncthreads();
        #pragma unroll
        for (int j = 0; j < 4; j++)
            *(u64*)&sm->h2[u0 + j][2 * r] = pack2(hn[j], hn[j]);
        if (gh == 0) sm->sp[w][r] = part;
        __syncthreads();

        if (w == 0 && gh == 0) {
            float O = ob;
            #pragma unroll
            for (int ww = 0; ww < 16; ww++) O += sm->sp[ww][r];
            if (l < LSEQ - 1) out[(b_row * (LSEQ - 1) + l) * NVAR + n] = O;
            else              out[PRED_OFF + b_row * NVAR + n] = O;
        }
    }
}

// ---------------- launch ----------------
extern "C" void kernel_launch(void* const* d_in, const int* in_sizes, int n_in,
                              void* d_out, int out_size) {
    (void)in_sizes; (void)n_in; (void)out_size;
    const float* X        = (const float*)d_in[0];
    const float* enc_Wih  = (const float*)d_in[1];
    const float* enc_Whh  = (const float*)d_in[2];
    const float* enc_bih  = (const float*)d_in[3];
    const float* enc_bhh  = (const float*)d_in[4];
    const float* pool_w   = (const float*)d_in[5];
    const float* pool_b   = (const float*)d_in[6];
    const float* Wqkv     = (const float*)d_in[7];
    const float* bqkv     = (const float*)d_in[8];
    const float* Wo       = (const float*)d_in[9];
    const float* bo       = (const float*)d_in[10];
    const float* dec_ih_W = (const float*)d_in[11];
    const float* dec_ih_b = (const float*)d_in[12];
    const float* dec_ic_W = (const float*)d_in[13];
    const float* dec_ic_b = (const float*)d_in[14];
    const float* dec_Whh  = (const float*)d_in[16];
    const float* dec_bih  = (const float*)d_in[17];
    const float* dec_bhh  = (const float*)d_in[18];
    const float* dec_out_W= (const float*)d_in[19];
    const float* dec_out_b= (const float*)d_in[20];
    float* out = (float*)d_out;

    static int attr_set = 0;
    if (!attr_set) {
        cudaFuncSetAttribute(mhsa_kernel, cudaFuncAttributeMaxDynamicSharedMemorySize, 66688);
        cudaFuncSetAttribute(enc_kernel,  cudaFuncAttributeMaxDynamicSharedMemorySize, SMEM_BYTES);
        cudaFuncSetAttribute(dec_kernel,  cudaFuncAttributeMaxDynamicSharedMemorySize, SMEM_BYTES);
        attr_set = 1;
    }

    float *pWtEnc, *pWtDec, *pWtIH, *pWtIC, *pWqkvT;
    cudaGetSymbolAddress((void**)&pWtEnc, g_WtEnc);
    cudaGetSymbolAddress((void**)&pWtDec, g_WtDec);
    cudaGetSymbolAddress((void**)&pWtIH,  g_WtIH);
    cudaGetSymbolAddress((void**)&pWtIC,  g_WtIC);
    cudaGetSymbolAddress((void**)&pWqkvT, g_WqkvT);

    dim3 tb(32, 8);
    transpose_kernel<<<dim3(4, 16, 32), tb>>>(enc_Whh,  pWtEnc, 512, 128);
    transpose_kernel<<<dim3(4, 16, 32), tb>>>(dec_Whh,  pWtDec, 512, 128);
    transpose_kernel<<<dim3(4,  4, 32), tb>>>(dec_ih_W, pWtIH,  128, 128);
    transpose_kernel<<<dim3(4,  4, 32), tb>>>(dec_ic_W, pWtIC,  128, 128);
    transpose_kernel<<<dim3(4, 12,  1), tb>>>(Wqkv,     pWqkvT, 384, 128);

    enc_kernel<<<dim3(PSPLIT, NVAR), 512, SMEM_BYTES>>>(X, enc_Wih, enc_bih, enc_bhh,
                                                        pool_w, pool_b);
    mhsa_kernel<<<BATCH, 128, 66688>>>(bqkv, Wo, bo, out);
    dec_kernel<<<dim3(PSPLIT, NVAR), 512, SMEM_BYTES>>>(dec_ih_b, dec_ic_b, dec_bih, dec_bhh,
                                                        dec_out_W, dec_out_b, out);
}

// round 14
// speedup vs baseline: 3.9633x; 3.9600x over previous
#include <cuda_runtime.h>
#include <cuda_bf16.h>

#define DD     128
#define GATES  512
#define BATCH  64
#define NVAR   32
#define LSEQ   128
#define BSUB   16
#define PSPLIT 4

#define PRED_OFF   260096
#define CSTAR_OFF  262144

#define NW     8          // warps per CTA
#define MT     4          // m-tiles per warp
#define KT9    9          // k-tiles (8 real + 1 for x/bias)
#define HSTR   76         // u32 words per hbuf row (152 bf16; k 0..151)

typedef unsigned long long u64;
typedef unsigned u32;

// ---------------- device scratch ----------------
// A fragments in "mma fragment order": uint4 per (n, w, mt, kt, lane)
__device__ __align__(16) uint4 g_AhiE[NVAR * NW * MT * KT9 * 32];
__device__ __align__(16) uint4 g_AloE[NVAR * NW * MT * KT9 * 32];
__device__ __align__(16) uint4 g_AhiD[NVAR * NW * MT * KT9 * 32];
__device__ __align__(16) uint4 g_AloD[NVAR * NW * MT * KT9 * 32];
__device__ __align__(16) float g_WqkvT[DD * 384];
__device__ __align__(16) float g_C    [BATCH * NVAR * DD];
__device__ __align__(16) float g_Cstar[BATCH * NVAR * DD];

// ---------------- scalar helpers ----------------
__device__ __forceinline__ u64 ffma2(u64 a, u64 b, u64 c) {
    u64 d; asm("fma.rn.f32x2 %0, %1, %2, %3;" : "=l"(d) : "l"(a), "l"(b), "l"(c)); return d;
}
__device__ __forceinline__ u64 pack2(float lo, float hi) {
    u64 r; asm("mov.b64 %0, {%1, %2};" : "=l"(r) : "f"(lo), "f"(hi)); return r;
}
__device__ __forceinline__ void unpack2(u64 v, float& lo, float& hi) {
    asm("mov.b64 {%0, %1}, %2;" : "=f"(lo), "=f"(hi) : "l"(v));
}
__device__ __forceinline__ float fsig(float x)  { return __fdividef(1.f, 1.f + __expf(-x)); }
__device__ __forceinline__ float ftanhf(float x){ return 1.f - __fdividef(2.f, __expf(2.f * x) + 1.f); }
__device__ __forceinline__ u32 smem_u32(const void* p) { return (u32)__cvta_generic_to_shared(p); }

__device__ __forceinline__ unsigned short f2bf(float x) {
    __nv_bfloat16 b = __float2bfloat16(x); return *(unsigned short*)&b;
}
__device__ __forceinline__ float bf2f(unsigned short s) {
    u32 v = ((u32)s) << 16; float f; asm("mov.b32 %0, %1;" : "=f"(f) : "r"(v)); return f;
}

__device__ __forceinline__ void mbar_init(u32 m, u32 c) {
    asm volatile("mbarrier.init.shared.b64 [%0], %1;" :: "r"(m), "r"(c) : "memory");
}
__device__ __forceinline__ void mbar_expect_tx(u32 m, u32 b) {
    asm volatile("mbarrier.arrive.expect_tx.shared.b64 _, [%0], %1;" :: "r"(m), "r"(b) : "memory");
}
__device__ __forceinline__ void mbar_wait(u32 m, u32 ph) {
    u32 done;
    asm volatile("{\n\t.reg .pred p;\n\t"
        "mbarrier.try_wait.parity.acquire.cta.shared::cta.b64 p, [%1], %2;\n\t"
        "selp.b32 %0, 1, 0, p;\n\t}" : "=r"(done) : "r"(m), "r"(ph) : "memory");
    if (!done) {
        asm volatile("{\n\t.reg .pred P1;\n\t"
            "W_%=:\n\t"
            "mbarrier.try_wait.parity.acquire.cta.shared::cta.b64 P1, [%0], %1, 0x989680;\n\t"
            "@P1 bra.uni DN_%=;\n\tbra.uni W_%=;\n\tDN_%=:\n\t}"
            :: "r"(m), "r"(ph) : "memory");
    }
}
__device__ __forceinline__ void bulk_copy(const void* g, void* s, u32 bytes, u32 m) {
    asm volatile(
        "cp.async.bulk.shared::cluster.global.mbarrier::complete_tx::bytes [%0], [%1], %2, [%3];"
        :: "r"(smem_u32(s)), "l"(g), "r"(bytes), "r"(m) : "memory");
}

__device__ __forceinline__ void mma16816(float* d, const u32* a, const u32* b) {
    asm volatile("mma.sync.aligned.m16n8k16.row.col.f32.bf16.bf16.f32 "
        "{%0,%1,%2,%3}, {%4,%5,%6,%7}, {%8,%9}, {%0,%1,%2,%3};"
        : "+f"(d[0]), "+f"(d[1]), "+f"(d[2]), "+f"(d[3])
        : "r"(a[0]), "r"(a[1]), "r"(a[2]), "r"(a[3]), "r"(b[0]), "r"(b[1]));
}

// ---------------- SMEM ----------------
struct __align__(16) SmemMMA {
    uint4 alo[NW * MT * KT9 * 32];    // 147456 B (kt8 region unused/zero)
    u32   hbuf[2][2][16 * HSTR];      // parity x (hi/lo) x 16 rows x 76 words = 19456 B
    float xs[2048];                   // enc: x[t][b]; dec: cs[k][b]
    float sp[2][NW][16];              // 1024 B
    u64   mbar[2];
};
#define SMEM_MMA ((int)sizeof(SmemMMA))

// ---------------- weight pack ----------------
// one thread per (n, w, mt, kt, lane) -> one uint4 in Ahi + one in Alo
__global__ void pack_w(const float* __restrict__ W, const float* __restrict__ Wih,
                       const float* __restrict__ bih, const float* __restrict__ bhh,
                       uint4* __restrict__ Ahi, uint4* __restrict__ Alo, int has_x) {
    int idx = blockIdx.x * 256 + threadIdx.x;   // (((n*8+w)*4+mt)*9+kt)*32+lane
    int lane = idx & 31;
    int kt   = (idx >> 5) % 9;
    int rest = (idx >> 5) / 9;
    int mt   = rest & 3;
    int w    = (rest >> 2) & 7;
    int n    = rest >> 5;
    int gid = lane >> 2, t = lane & 3;
    u32 hi[4], lo[4];
    #pragma unroll
    for (int rr = 0; rr < 4; rr++) {
        int row   = (rr & 1) ? gid + 8 : gid;
        int cbase = (rr >> 1) ? 2 * t + 8 : 2 * t;
        int u    = 16 * w + ((mt >> 1) << 3) + (row & 7);
        int gate = ((mt & 1) << 1) + (row >> 3);
        u32 hv = 0, lv = 0;
        #pragma unroll
        for (int e = 0; e < 2; e++) {
            int col = cbase + e;
            unsigned short hb = 0, lb = 0;
            if (kt < 8) {
                float v = W[((size_t)n * GATES + gate * 128 + u) * DD + kt * 16 + col];
                hb = f2bf(v);
                lb = f2bf(v - bf2f(hb));
            } else {
                if (col == 0 || col == 1) {
                    float wv = has_x ? Wih[(size_t)n * GATES + gate * 128 + u] : 0.f;
                    unsigned short wh = f2bf(wv);
                    hb = (col == 0) ? wh : f2bf(wv - bf2f(wh));
                } else if (col == 2 || col == 3) {
                    float bv = bih[(size_t)n * GATES + gate * 128 + u]
                             + bhh[(size_t)n * GATES + gate * 128 + u];
                    unsigned short bh16 = f2bf(bv);
                    hb = (col == 2) ? bh16 : f2bf(bv - bf2f(bh16));
                }
                lb = 0;
            }
            hv |= ((u32)hb) << (16 * e);
            lv |= ((u32)lb) << (16 * e);
        }
        hi[rr] = hv; lo[rr] = lv;
    }
    Ahi[idx] = make_uint4(hi[0], hi[1], hi[2], hi[3]);
    Alo[idx] = make_uint4(lo[0], lo[1], lo[2], lo[3]);
}

__global__ void transpose_kernel(const float* __restrict__ src, float* __restrict__ dst, int R, int C) {
    __shared__ float tile[32][33];
    int c0 = blockIdx.x * 32, r0 = blockIdx.y * 32;
    #pragma unroll
    for (int i = threadIdx.y; i < 32; i += 8)
        tile[i][threadIdx.x] = src[(r0 + i) * C + c0 + threadIdx.x];
    __syncthreads();
    #pragma unroll
    for (int i = threadIdx.y; i < 32; i += 8)
        dst[(c0 + i) * R + r0 + threadIdx.x] = tile[threadIdx.x][i];
}

// ---------------- per-step GEMM: acc[mt][nt][4] += W x h (3-term bf16 split) ----------------
__device__ __forceinline__ void do_mma_step(
    const uint4* __restrict__ aloW, const u32* __restrict__ rb_hi, const u32* __restrict__ rb_lo,
    const u32* __restrict__ ahi, float acc[4][2][4], int lane)
{
    int gid = lane >> 2, t = lane & 3;
    int b0o = gid * HSTR + t;
    int b1o = b0o + 8 * HSTR;
    #pragma unroll
    for (int kt = 0; kt < KT9; kt++) {
        int wo = kt * 8;
        u32 bh[2][2], bl[2][2];
        bh[0][0] = rb_hi[b0o + wo]; bh[0][1] = rb_hi[b0o + wo + 4];
        bh[1][0] = rb_hi[b1o + wo]; bh[1][1] = rb_hi[b1o + wo + 4];
        bl[0][0] = rb_lo[b0o + wo]; bl[0][1] = rb_lo[b0o + wo + 4];
        bl[1][0] = rb_lo[b1o + wo]; bl[1][1] = rb_lo[b1o + wo + 4];
        #pragma unroll
        for (int mt = 0; mt < 4; mt++) {
            const u32* ah = ahi + (mt * KT9 + kt) * 4;
            u32 al[4];
            if (kt < 8) {
                uint4 v = aloW[(mt * KT9 + kt) * 32 + lane];
                al[0] = v.x; al[1] = v.y; al[2] = v.z; al[3] = v.w;
            }
            #pragma unroll
            for (int nt = 0; nt < 2; nt++) {
                mma16816(acc[mt][nt], ah, bh[nt]);
                mma16816(acc[mt][nt], ah, bl[nt]);
                if (kt < 8) mma16816(acc[mt][nt], al, bh[nt]);
            }
        }
    }
}

// write h (fp32) as bf16 hi/lo into write-buffer at row n=col, k=u
__device__ __forceinline__ void store_h(u32 hbase_hi, u32 hbase_lo, int col, int u, float h) {
    u32 byte = (u32)(col * HSTR + (u >> 1)) * 4 + (u & 1) * 2;
    unsigned short hb = f2bf(h);
    unsigned short lb = f2bf(h - bf2f(hb));
    asm volatile("st.shared.b16 [%0], %1;" :: "r"(hbase_hi + byte), "h"(hb) : "memory");
    asm volatile("st.shared.b16 [%0], %1;" :: "r"(hbase_lo + byte), "h"(lb) : "memory");
}

// ================= encoder =================
__global__ __launch_bounds__(256, 1) void enc_kernel(
    const float* __restrict__ X,
    const float* __restrict__ pool_w, const float* __restrict__ pool_b) {
    extern __shared__ __align__(16) char smraw[];
    SmemMMA* sm = (SmemMMA*)smraw;
    const int nv = blockIdx.y, p = blockIdx.x;
    const int tid = threadIdx.x, lane = tid & 31, w = tid >> 5;
    const int gid = lane >> 2, t = lane & 3;
    u32 mbA = smem_u32(&sm->mbar[0]);

    if (tid == 0) {
        mbar_init(mbA, 1);
        mbar_expect_tx(mbA, 147456);
        const char* src = (const char*)(g_AloE + (size_t)nv * (NW * MT * KT9 * 32));
        bulk_copy(src,          sm->alo,                 73728, mbA);
        bulk_copy(src + 73728, (char*)sm->alo + 73728,   73728, mbA);
    }
    // zero hbuf
    for (int i = tid; i < 2 * 2 * 16 * HSTR; i += 256) ((u32*)sm->hbuf)[i] = 0;
    // stage X: xs[t][b]
    for (int i = tid; i < 2048; i += 256) {
        int b = i & 15, tt = i >> 4;
        sm->xs[i] = X[((size_t)(p * BSUB + b) * LSEQ + tt) * NVAR + nv];
    }
    // load A_hi fragments into registers
    u32 ahi[MT * KT9 * 4];
    {
        const uint4* gA = g_AhiE + ((size_t)nv * NW + w) * (MT * KT9 * 32);
        #pragma unroll
        for (int f = 0; f < MT * KT9; f++) {
            uint4 v = gA[f * 32 + lane];
            ahi[f * 4] = v.x; ahi[f * 4 + 1] = v.y; ahi[f * 4 + 2] = v.z; ahi[f * 4 + 3] = v.w;
        }
    }
    __syncthreads();
    // constants: B_hi rows k=130,131 = 1.0 (both parities); write x(0) into parity0
    if (tid < 32) {
        int par = tid >> 4, nn = tid & 15;
        sm->hbuf[par][0][nn * HSTR + 65] = 0x3F803F80u;
    }
    if (tid < 16) {
        float x = sm->xs[tid];
        unsigned short xh = f2bf(x);
        unsigned short xl = f2bf(x - bf2f(xh));
        sm->hbuf[0][0][tid * HSTR + 64] = (u32)xh | ((u32)xh << 16);
        sm->hbuf[0][1][tid * HSTR + 64] = (u32)xl;
    }
    mbar_wait(mbA, 0);
    __syncthreads();

    const int u0 = 16 * w + gid, u1 = u0 + 8;
    const float pw0 = pool_w[nv * DD + u0], pw1 = pool_w[nv * DD + u1];
    const float pb = pool_b[nv];
    float c[2][4], accC[2][4], pm[4], pss[4];
    #pragma unroll
    for (int j = 0; j < 4; j++) {
        c[0][j] = c[1][j] = 0.f; accC[0][j] = accC[1][j] = 0.f;
        pm[j] = -1e30f; pss[j] = 0.f;
    }
    int cols[4];
    #pragma unroll
    for (int j = 0; j < 4; j++) cols[j] = (j >> 1) * 8 + 2 * t + (j & 1);
    const uint4* aloW = sm->alo + w * (MT * KT9 * 32);

    for (int ts = 0; ts < LSEQ - 1; ts++) {
        int par = ts & 1;
        float acc[4][2][4];
        #pragma unroll
        for (int mt = 0; mt < 4; mt++)
            #pragma unroll
            for (int nt = 0; nt < 2; nt++)
                #pragma unroll
                for (int r = 0; r < 4; r++) acc[mt][nt][r] = 0.f;
        do_mma_step(aloW, sm->hbuf[par][0], sm->hbuf[par][1], ahi, acc, lane);

        // gates (all in-lane)
        float h[2][4];
        #pragma unroll
        for (int ui = 0; ui < 2; ui++) {
            int mb = ui * 2;
            #pragma unroll
            for (int j = 0; j < 4; j++) {
                int nt = j >> 1, ci = j & 1;
                float pi = acc[mb][nt][ci],     pf = acc[mb][nt][2 + ci];
                float pg = acc[mb + 1][nt][ci], po = acc[mb + 1][nt][2 + ci];
                float cn = fsig(pf) * c[ui][j] + fsig(pi) * ftanhf(pg);
                c[ui][j] = cn;
                h[ui][j] = fsig(po) * ftanhf(cn);
            }
        }
        // write h + next x to write-buffer
        u32 hb_hi = smem_u32(sm->hbuf[par ^ 1][0]);
        u32 hb_lo = smem_u32(sm->hbuf[par ^ 1][1]);
        #pragma unroll
        for (int j = 0; j < 4; j++) {
            store_h(hb_hi, hb_lo, cols[j], u0, h[0][j]);
            store_h(hb_hi, hb_lo, cols[j], u1, h[1][j]);
        }
        if (tid < 16) {
            float x = sm->xs[(ts + 1) * 16 + tid];
            unsigned short xh = f2bf(x);
            unsigned short xl = f2bf(x - bf2f(xh));
            sm->hbuf[par ^ 1][0][tid * HSTR + 64] = (u32)xh | ((u32)xh << 16);
            sm->hbuf[par ^ 1][1][tid * HSTR + 64] = (u32)xl;
        }
        // pooling partials
        float part[4];
        #pragma unroll
        for (int j = 0; j < 4; j++) part[j] = h[0][j] * pw0 + h[1][j] * pw1;
        #pragma unroll
        for (int off = 4; off <= 16; off <<= 1)
            #pragma unroll
            for (int j = 0; j < 4; j++)
                part[j] += __shfl_xor_sync(0xffffffffu, part[j], off);
        if (gid == 0)
            #pragma unroll
            for (int j = 0; j < 4; j++) sm->sp[par][w][cols[j]] = part[j];
        __syncthreads();
        #pragma unroll
        for (int j = 0; j < 4; j++) {
            float s = pb;
            #pragma unroll
            for (int ww = 0; ww < NW; ww++) s += sm->sp[par][ww][cols[j]];
            float mn = fmaxf(pm[j], s);
            float scale = __expf(pm[j] - mn);
            float wcur  = __expf(s - mn);
            pss[j] = pss[j] * scale + wcur;
            pm[j] = mn;
            accC[0][j] = accC[0][j] * scale + wcur * h[0][j];
            accC[1][j] = accC[1][j] * scale + wcur * h[1][j];
        }
    }
    #pragma unroll
    for (int j = 0; j < 4; j++) {
        int b = p * BSUB + cols[j];
        float iv = __fdividef(1.f, pss[j]);
        g_C[((size_t)b * NVAR + nv) * DD + u0] = accC[0][j] * iv;
        g_C[((size_t)b * NVAR + nv) * DD + u1] = accC[1][j] * iv;
    }
}

// ================= MHSA (CUDA-core, tiny) =================
__global__ __launch_bounds__(128, 1) void mhsa_kernel(
    const float* __restrict__ bqkv,
    const float* __restrict__ Wo, const float* __restrict__ bo,
    float* __restrict__ out) {
    extern __shared__ __align__(16) float smf[];
    float* Cs  = smf;
    float* QKV = smf + 4352;
    float* As  = smf;
    const int b = blockIdx.x, tid = threadIdx.x;

    #pragma unroll 4
    for (int i = 0; i < 32; i++)
        Cs[tid * 34 + i] = g_C[(b * NVAR + i) * DD + tid];
    __syncthreads();

    for (int jj = 0; jj < 3; jj++) {
        int j = jj * 128 + tid;
        float bj = bqkv[j];
        u64 acc[16];
        #pragma unroll
        for (int vp = 0; vp < 16; vp++) acc[vp] = pack2(bj, bj);
        #pragma unroll 2
        for (int k = 0; k < DD; k++) {
            float wv = g_WqkvT[k * 384 + j];
            u64 ww = pack2(wv, wv);
            const u64* crow = (const u64*)&Cs[k * 34];
            #pragma unroll
            for (int vp = 0; vp < 16; vp++) acc[vp] = ffma2(ww, crow[vp], acc[vp]);
        }
        #pragma unroll
        for (int vp = 0; vp < 16; vp++) {
            float a0, a1; unpack2(acc[vp], a0, a1);
            QKV[(2 * vp)     * 385 + j] = a0;
            QKV[(2 * vp + 1) * 385 + j] = a1;
        }
    }
    __syncthreads();
    {
        int h = tid >> 5, i = tid & 31;
        float q[32];
        #pragma unroll
        for (int d = 0; d < 32; d++) q[d] = QKV[i * 385 + h * 32 + d];
        float s[32];
        #pragma unroll
        for (int j = 0; j < 32; j++) {
            float a = 0.f;
            #pragma unroll
            for (int d = 0; d < 32; d++) a += q[d] * QKV[j * 385 + 128 + h * 32 + d];
            s[j] = a * 0.17677669529663687f;
        }
        float mx = s[0];
        #pragma unroll
        for (int j = 1; j < 32; j++) mx = fmaxf(mx, s[j]);
        float sum = 0.f;
        #pragma unroll
        for (int j = 0; j < 32; j++) { s[j] = __expf(s[j] - mx); sum += s[j]; }
        float inv = __fdividef(1.f, sum);
        float A[32];
        #pragma unroll
        for (int d = 0; d < 32; d++) A[d] = 0.f;
        #pragma unroll
        for (int j = 0; j < 32; j++) {
            float aj = s[j] * inv;
            #pragma unroll
            for (int d = 0; d < 32; d++) A[d] += aj * QKV[j * 385 + 256 + h * 32 + d];
        }
        #pragma unroll
        for (int d = 0; d < 32; d++) As[i * 129 + h * 32 + d] = A[d];
    }
    __syncthreads();
    {
        int v = tid & 31, uc = tid >> 5;
        for (int mm = 0; mm < 32; mm++) {
            int u = uc * 32 + mm;
            float a = bo[u];
            #pragma unroll 4
            for (int d = 0; d < DD; d++) a += As[v * 129 + d] * Wo[u * DD + d];
            g_Cstar[(b * NVAR + v) * DD + u] = a;
            out[CSTAR_OFF + (b * NVAR + v) * DD + u] = a;
        }
    }
}

// ================= decoder =================
__global__ __launch_bounds__(256, 1) void dec_kernel(
    const float* __restrict__ ihW, const float* __restrict__ ihB,
    const float* __restrict__ icW, const float* __restrict__ icB,
    const float* __restrict__ outW, const float* __restrict__ outB,
    float* __restrict__ out) {
    extern __shared__ __align__(16) char smraw[];
    SmemMMA* sm = (SmemMMA*)smraw;
    const int nv = blockIdx.y, p = blockIdx.x;
    const int tid = threadIdx.x, lane = tid & 31, w = tid >> 5;
    const int gid = lane >> 2, t = lane & 3;
    u32 mbA = smem_u32(&sm->mbar[0]);

    if (tid == 0) {
        mbar_init(mbA, 1);
        mbar_expect_tx(mbA, 147456);
        const char* src = (const char*)(g_AloD + (size_t)nv * (NW * MT * KT9 * 32));
        bulk_copy(src,          sm->alo,                73728, mbA);
        bulk_copy(src + 73728, (char*)sm->alo + 73728,  73728, mbA);
    }
    for (int i = tid; i < 2 * 2 * 16 * HSTR; i += 256) ((u32*)sm->hbuf)[i] = 0;
    // stage cs: xs[k][b]
    for (int i = tid; i < 2048; i += 256) {
        int b = i & 15, k = i >> 4;
        sm->xs[i] = g_Cstar[((size_t)(p * BSUB + b) * NVAR + nv) * DD + k];
    }
    u32 ahi[MT * KT9 * 4];
    {
        const uint4* gA = g_AhiD + ((size_t)nv * NW + w) * (MT * KT9 * 32);
        #pragma unroll
        for (int f = 0; f < MT * KT9; f++) {
            uint4 v = gA[f * 32 + lane];
            ahi[f * 4] = v.x; ahi[f * 4 + 1] = v.y; ahi[f * 4 + 2] = v.z; ahi[f * 4 + 3] = v.w;
        }
    }
    __syncthreads();
    if (tid < 32) {
        int par = tid >> 4, nn = tid & 15;
        sm->hbuf[par][0][nn * HSTR + 65] = 0x3F803F80u;   // bias*1 rows
    }

    const int u0 = 16 * w + gid, u1 = u0 + 8;
    int cols[4];
    #pragma unroll
    for (int j = 0; j < 4; j++) cols[j] = (j >> 1) * 8 + 2 * t + (j & 1);

    // init matvecs: h0 = tanh(cs@ihW^T + ihB), c0 = tanh(cs@icW^T + icB)
    float c[2][4], h0[2][4];
    {
        float ah0[4], ah1[4], ac0[4], ac1[4];
        float bh0 = ihB[nv * DD + u0], bh1 = ihB[nv * DD + u1];
        float bc0 = icB[nv * DD + u0], bc1 = icB[nv * DD + u1];
        #pragma unroll
        for (int j = 0; j < 4; j++) { ah0[j] = bh0; ah1[j] = bh1; ac0[j] = bc0; ac1[j] = bc1; }
        const float* wh0 = ihW + ((size_t)nv * DD + u0) * DD;
        const float* wh1 = ihW + ((size_t)nv * DD + u1) * DD;
        const float* wc0 = icW + ((size_t)nv * DD + u0) * DD;
        const float* wc1 = icW + ((size_t)nv * DD + u1) * DD;
        #pragma unroll 2
        for (int k = 0; k < DD; k++) {
            float a0 = wh0[k], a1 = wh1[k], b0 = wc0[k], b1 = wc1[k];
            #pragma unroll
            for (int j = 0; j < 4; j++) {
                float cv = sm->xs[k * 16 + cols[j]];
                ah0[j] += a0 * cv; ah1[j] += a1 * cv;
                ac0[j] += b0 * cv; ac1[j] += b1 * cv;
            }
        }
        #pragma unroll
        for (int j = 0; j < 4; j++) {
            h0[0][j] = ftanhf(ah0[j]); h0[1][j] = ftanhf(ah1[j]);
            c[0][j]  = ftanhf(ac0[j]); c[1][j]  = ftanhf(ac1[j]);
        }
    }
    __syncthreads();   // done reading staged cs; hbuf zero/const complete
    {
        u32 hb_hi = smem_u32(sm->hbuf[0][0]);
        u32 hb_lo = smem_u32(sm->hbuf[0][1]);
        #pragma unroll
        for (int j = 0; j < 4; j++) {
            store_h(hb_hi, hb_lo, cols[j], u0, h0[0][j]);
            store_h(hb_hi, hb_lo, cols[j], u1, h0[1][j]);
        }
    }
    mbar_wait(mbA, 0);
    __syncthreads();

    const float wo0 = outW[nv * DD + u0], wo1 = outW[nv * DD + u1];
    const float ob = outB[nv];
    const uint4* aloW = sm->alo + w * (MT * KT9 * 32);
    const int b_row0 = p * BSUB;

    for (int l = 0; l < LSEQ; l++) {
        int par = l & 1;
        float acc[4][2][4];
        #pragma unroll
        for (int mt = 0; mt < 4; mt++)
            #pragma unroll
            for (int nt = 0; nt < 2; nt++)
                #pragma unroll
                for (int r = 0; r < 4; r++) acc[mt][nt][r] = 0.f;
        do_mma_step(aloW, sm->hbuf[par][0], sm->hbuf[par][1], ahi, acc, lane);

        float h[2][4];
        #pragma unroll
        for (int ui = 0; ui < 2; ui++) {
            int mb = ui * 2;
            #pragma unroll
            for (int j = 0; j < 4; j++) {
                int nt = j >> 1, ci = j & 1;
                float pi = acc[mb][nt][ci],     pf = acc[mb][nt][2 + ci];
                float pg = acc[mb + 1][nt][ci], po = acc[mb + 1][nt][2 + ci];
                float cn = fsig(pf) * c[ui][j] + fsig(pi) * ftanhf(pg);
                c[ui][j] = cn;
                h[ui][j] = fsig(po) * ftanhf(cn);
            }
        }
        u32 hb_hi = smem_u32(sm->hbuf[par ^ 1][0]);
        u32 hb_lo = smem_u32(sm->hbuf[par ^ 1][1]);
        #pragma unroll
        for (int j = 0; j < 4; j++) {
            store_h(hb_hi, hb_lo, cols[j], u0, h[0][j]);
            store_h(hb_hi, hb_lo, cols[j], u1, h[1][j]);
        }
        float part[4];
        #pragma unroll
        for (int j = 0; j < 4; j++) part[j] = h[0][j] * wo0 + h[1][j] * wo1;
        #pragma unroll
        for (int off = 4; off <= 16; off <<= 1)
            #pragma unroll
            for (int j = 0; j < 4; j++)
                part[j] += __shfl_xor_sync(0xffffffffu, part[j], off);
        if (gid == 0)
            #pragma unroll
            for (int j = 0; j < 4; j++) sm->sp[par][w][cols[j]] = part[j];
        __syncthreads();
        if (tid < 16) {
            float O = ob;
            #pragma unroll
            for (int ww = 0; ww < NW; ww++) O += sm->sp[par][ww][tid];
            int b = b_row0 + tid;
            if (l < LSEQ - 1) out[((size_t)b * (LSEQ - 1) + l) * NVAR + nv] = O;
            else              out[PRED_OFF + b * NVAR + nv] = O;
        }
    }
}

// ---------------- launch ----------------
extern "C" void kernel_launch(void* const* d_in, const int* in_sizes, int n_in,
                              void* d_out, int out_size) {
    (void)in_sizes; (void)n_in; (void)out_size;
    const float* X        = (const float*)d_in[0];
    const float* enc_Wih  = (const float*)d_in[1];
    const float* enc_Whh  = (const float*)d_in[2];
    const float* enc_bih  = (const float*)d_in[3];
    const float* enc_bhh  = (const float*)d_in[4];
    const float* pool_w   = (const float*)d_in[5];
    const float* pool_b   = (const float*)d_in[6];
    const float* Wqkv     = (const float*)d_in[7];
    const float* bqkv     = (const float*)d_in[8];
    const float* Wo       = (const float*)d_in[9];
    const float* bo       = (const float*)d_in[10];
    const float* dec_ih_W = (const float*)d_in[11];
    const float* dec_ih_b = (const float*)d_in[12];
    const float* dec_ic_W = (const float*)d_in[13];
    const float* dec_ic_b = (const float*)d_in[14];
    const float* dec_Wih  = (const float*)d_in[15];
    const float* dec_Whh  = (const float*)d_in[16];
    const float* dec_bih  = (const float*)d_in[17];
    const float* dec_bhh  = (const float*)d_in[18];
    const float* dec_out_W= (const float*)d_in[19];
    const float* dec_out_b= (const float*)d_in[20];
    float* out = (float*)d_out;

    static int attr_set = 0;
    if (!attr_set) {
        cudaFuncSetAttribute(mhsa_kernel, cudaFuncAttributeMaxDynamicSharedMemorySize, 66688);
        cudaFuncSetAttribute(enc_kernel,  cudaFuncAttributeMaxDynamicSharedMemorySize, SMEM_MMA);
        cudaFuncSetAttribute(dec_kernel,  cudaFuncAttributeMaxDynamicSharedMemorySize, SMEM_MMA);
        attr_set = 1;
    }

    uint4 *pAhiE, *pAloE, *pAhiD, *pAloD; float* pWqkvT;
    cudaGetSymbolAddress((void**)&pAhiE, g_AhiE);
    cudaGetSymbolAddress((void**)&pAloE, g_AloE);
    cudaGetSymbolAddress((void**)&pAhiD, g_AhiD);
    cudaGetSymbolAddress((void**)&pAloD, g_AloD);
    cudaGetSymbolAddress((void**)&pWqkvT, g_WqkvT);

    pack_w<<<1152, 256>>>(enc_Whh, enc_Wih, enc_bih, enc_bhh, pAhiE, pAloE, 1);
    pack_w<<<1152, 256>>>(dec_Whh, dec_Wih, dec_bih, dec_bhh, pAhiD, pAloD, 0);
    transpose_kernel<<<dim3(4, 12, 1), dim3(32, 8)>>>(Wqkv, pWqkvT, 384, 128);

    enc_kernel<<<dim3(PSPLIT, NVAR), 256, SMEM_MMA>>>(X, pool_w, pool_b);
    mhsa_kernel<<<BATCH, 128, 66688>>>(bqkv, Wo, bo, out);
    dec_kernel<<<dim3(PSPLIT, NVAR), 256, SMEM_MMA>>>(dec_ih_W, dec_ih_b, dec_ic_W, dec_ic_b,
                                                      dec_out_W, dec_out_b, out);
}

// round 15
// speedup vs baseline: 4.0570x; 1.0236x over previous
#include <cuda_runtime.h>
#include <cuda_bf16.h>

#define DD     128
#define GATES  512
#define BATCH  64
#define NVAR   32
#define LSEQ   128
#define BSUB   16
#define PSPLIT 4

#define PRED_OFF   260096
#define CSTAR_OFF  262144

#define NW     8          // warps per CTA
#define MT     4          // m-tiles per warp
#define KT9    9          // k-tiles (8 real + 1 for x/bias)
#define HSTR   76         // u32 words per hbuf row (152 bf16; k 0..151)
#define HBUF_W (8 * HSTR) // words per (group,par,hl) buffer: 8 rows
#define HBUF_B (HBUF_W * 4)

typedef unsigned long long u64;
typedef unsigned u32;

// ---------------- device scratch ----------------
__device__ __align__(16) uint4 g_AhiE[NVAR * NW * MT * KT9 * 32];
__device__ __align__(16) uint4 g_AloE[NVAR * NW * MT * KT9 * 32];
__device__ __align__(16) uint4 g_AhiD[NVAR * NW * MT * KT9 * 32];
__device__ __align__(16) uint4 g_AloD[NVAR * NW * MT * KT9 * 32];
__device__ __align__(16) float g_WqkvT[DD * 384];
__device__ __align__(16) float g_C    [BATCH * NVAR * DD];
__device__ __align__(16) float g_Cstar[BATCH * NVAR * DD];

// ---------------- scalar helpers ----------------
__device__ __forceinline__ u64 ffma2(u64 a, u64 b, u64 c) {
    u64 d; asm("fma.rn.f32x2 %0, %1, %2, %3;" : "=l"(d) : "l"(a), "l"(b), "l"(c)); return d;
}
__device__ __forceinline__ u64 pack2(float lo, float hi) {
    u64 r; asm("mov.b64 %0, {%1, %2};" : "=l"(r) : "f"(lo), "f"(hi)); return r;
}
__device__ __forceinline__ void unpack2(u64 v, float& lo, float& hi) {
    asm("mov.b64 {%0, %1}, %2;" : "=f"(lo), "=f"(hi) : "l"(v));
}
__device__ __forceinline__ float fsig(float x)  { return __fdividef(1.f, 1.f + __expf(-x)); }
__device__ __forceinline__ float ftanhf(float x){ return 1.f - __fdividef(2.f, __expf(2.f * x) + 1.f); }
__device__ __forceinline__ u32 smem_u32(const void* p) { return (u32)__cvta_generic_to_shared(p); }

__device__ __forceinline__ unsigned short f2bf(float x) {
    __nv_bfloat16 b = __float2bfloat16(x); return *(unsigned short*)&b;
}
__device__ __forceinline__ float bf2f(unsigned short s) {
    u32 v = ((u32)s) << 16; float f; asm("mov.b32 %0, %1;" : "=f"(f) : "r"(v)); return f;
}

__device__ __forceinline__ void mbar_init(u32 m, u32 c) {
    asm volatile("mbarrier.init.shared.b64 [%0], %1;" :: "r"(m), "r"(c) : "memory");
}
__device__ __forceinline__ void mbar_expect_tx(u32 m, u32 b) {
    asm volatile("mbarrier.arrive.expect_tx.shared.b64 _, [%0], %1;" :: "r"(m), "r"(b) : "memory");
}
__device__ __forceinline__ void mbar_wait(u32 m, u32 ph) {
    u32 done;
    asm volatile("{\n\t.reg .pred p;\n\t"
        "mbarrier.try_wait.parity.acquire.cta.shared::cta.b64 p, [%1], %2;\n\t"
        "selp.b32 %0, 1, 0, p;\n\t}" : "=r"(done) : "r"(m), "r"(ph) : "memory");
    if (!done) {
        asm volatile("{\n\t.reg .pred P1;\n\t"
            "W_%=:\n\t"
            "mbarrier.try_wait.parity.acquire.cta.shared::cta.b64 P1, [%0], %1, 0x989680;\n\t"
            "@P1 bra.uni DN_%=;\n\tbra.uni W_%=;\n\tDN_%=:\n\t}"
            :: "r"(m), "r"(ph) : "memory");
    }
}
__device__ __forceinline__ void bulk_copy(const void* g, void* s, u32 bytes, u32 m) {
    asm volatile(
        "cp.async.bulk.shared::cluster.global.mbarrier::complete_tx::bytes [%0], [%1], %2, [%3];"
        :: "r"(smem_u32(s)), "l"(g), "r"(bytes), "r"(m) : "memory");
}

__device__ __forceinline__ void mma16816(float* d, const u32* a, const u32* b) {
    asm volatile("mma.sync.aligned.m16n8k16.row.col.f32.bf16.bf16.f32 "
        "{%0,%1,%2,%3}, {%4,%5,%6,%7}, {%8,%9}, {%0,%1,%2,%3};"
        : "+f"(d[0]), "+f"(d[1]), "+f"(d[2]), "+f"(d[3])
        : "r"(a[0]), "r"(a[1]), "r"(a[2]), "r"(a[3]), "r"(b[0]), "r"(b[1]));
}

// ---------------- SMEM ----------------
struct __align__(16) SmemMMA {
    uint4 alo[NW * MT * KT9 * 32];     // 147456 B
    u32   hbuf[8][HBUF_W];             // [g*4+par*2+hl][8 rows x 76 words] = 19456 B
    float xs[2048];                    // enc: x[t][b]; dec: cs[k][b]
    float sp[NW][16];                  // 512 B
    u64   mbar[2];
};
#define SMEM_MMA ((int)sizeof(SmemMMA))

// ---------------- weight pack (unchanged layout from R13) ----------------
__global__ void pack_w(const float* __restrict__ W, const float* __restrict__ Wih,
                       const float* __restrict__ bih, const float* __restrict__ bhh,
                       uint4* __restrict__ Ahi, uint4* __restrict__ Alo, int has_x) {
    int idx = blockIdx.x * 256 + threadIdx.x;
    int lane = idx & 31;
    int kt   = (idx >> 5) % 9;
    int rest = (idx >> 5) / 9;
    int mt   = rest & 3;
    int w    = (rest >> 2) & 7;
    int n    = rest >> 5;
    int gid = lane >> 2, t = lane & 3;
    u32 hi[4], lo[4];
    #pragma unroll
    for (int rr = 0; rr < 4; rr++) {
        int row   = (rr & 1) ? gid + 8 : gid;
        int cbase = (rr >> 1) ? 2 * t + 8 : 2 * t;
        int u    = 16 * w + ((mt >> 1) << 3) + (row & 7);
        int gate = ((mt & 1) << 1) + (row >> 3);
        u32 hv = 0, lv = 0;
        #pragma unroll
        for (int e = 0; e < 2; e++) {
            int col = cbase + e;
            unsigned short hb = 0, lb = 0;
            if (kt < 8) {
                float v = W[((size_t)n * GATES + gate * 128 + u) * DD + kt * 16 + col];
                hb = f2bf(v);
                lb = f2bf(v - bf2f(hb));
            } else {
                if (col == 0 || col == 1) {
                    float wv = has_x ? Wih[(size_t)n * GATES + gate * 128 + u] : 0.f;
                    unsigned short wh = f2bf(wv);
                    hb = (col == 0) ? wh : f2bf(wv - bf2f(wh));
                } else if (col == 2 || col == 3) {
                    float bv = bih[(size_t)n * GATES + gate * 128 + u]
                             + bhh[(size_t)n * GATES + gate * 128 + u];
                    unsigned short bh16 = f2bf(bv);
                    hb = (col == 2) ? bh16 : f2bf(bv - bf2f(bh16));
                }
                lb = 0;
            }
            hv |= ((u32)hb) << (16 * e);
            lv |= ((u32)lb) << (16 * e);
        }
        hi[rr] = hv; lo[rr] = lv;
    }
    Ahi[idx] = make_uint4(hi[0], hi[1], hi[2], hi[3]);
    Alo[idx] = make_uint4(lo[0], lo[1], lo[2], lo[3]);
}

__global__ void transpose_kernel(const float* __restrict__ src, float* __restrict__ dst, int R, int C) {
    __shared__ float tile[32][33];
    int c0 = blockIdx.x * 32, r0 = blockIdx.y * 32;
    #pragma unroll
    for (int i = threadIdx.y; i < 32; i += 8)
        tile[i][threadIdx.x] = src[(r0 + i) * C + c0 + threadIdx.x];
    __syncthreads();
    #pragma unroll
    for (int i = threadIdx.y; i < 32; i += 8)
        dst[(c0 + i) * R + r0 + threadIdx.x] = tile[threadIdx.x][i];
}

// ---------------- per-group GEMM: acc[4][4] += W x h_g (3-term bf16 split) ----------------
__device__ __forceinline__ void do_mma_g(
    const uint4* __restrict__ aloW, const u32* __restrict__ hb,
    const u32* __restrict__ ahi, float acc[4][4], int lane)
{
    int gid = lane >> 2, t = lane & 3;
    int bo = gid * HSTR + t;
    const u32* hl = hb + HBUF_W;   // lo buffer adjacent
    #pragma unroll
    for (int kt = 0; kt < KT9; kt++) {
        int wo = kt * 8;
        u32 bh[2] = { hb[bo + wo], hb[bo + wo + 4] };
        u32 bl[2] = { hl[bo + wo], hl[bo + wo + 4] };
        #pragma unroll
        for (int mt = 0; mt < 4; mt++) {
            const u32* ah = ahi + (mt * KT9 + kt) * 4;
            mma16816(acc[mt], ah, bh);
            mma16816(acc[mt], ah, bl);
            if (kt < 8) {
                uint4 v = aloW[(mt * KT9 + kt) * 32 + lane];
                u32 al[4] = {v.x, v.y, v.z, v.w};
                mma16816(acc[mt], al, bh);
            }
        }
    }
}

// gates for one group (2 cols x 2 units per thread)
__device__ __forceinline__ void gates_group(const float acc[4][4], float c[2][2], float h[2][2]) {
    #pragma unroll
    for (int ui = 0; ui < 2; ui++) {
        int mb = 2 * ui;
        #pragma unroll
        for (int j = 0; j < 2; j++) {
            float pi = acc[mb][j],     pf = acc[mb][2 + j];
            float pg = acc[mb + 1][j], po = acc[mb + 1][2 + j];
            float cn = fsig(pf) * c[ui][j] + fsig(pi) * ftanhf(pg);
            c[ui][j] = cn;
            h[ui][j] = fsig(po) * ftanhf(cn);
        }
    }
}

__device__ __forceinline__ void store_hv(u32 hibase, int cg, int u, float h) {
    u32 byte = (u32)(cg * HSTR + (u >> 1)) * 4 + (u & 1) * 2;
    unsigned short hb = f2bf(h);
    unsigned short lb = f2bf(h - bf2f(hb));
    asm volatile("st.shared.b16 [%0], %1;" :: "r"(hibase + byte), "h"(hb) : "memory");
    asm volatile("st.shared.b16 [%0], %1;" :: "r"(hibase + HBUF_B + byte), "h"(lb) : "memory");
}
__device__ __forceinline__ void store_group(u32 hibase, const float h[2][2], int t, int u0, int u1) {
    #pragma unroll
    for (int j = 0; j < 2; j++) {
        store_hv(hibase, 2 * t + j, u0, h[0][j]);
        store_hv(hibase, 2 * t + j, u1, h[1][j]);
    }
}

// ================= encoder =================
__global__ __launch_bounds__(256, 1) void enc_kernel(
    const float* __restrict__ X,
    const float* __restrict__ pool_w, const float* __restrict__ pool_b) {
    extern __shared__ __align__(16) char smraw[];
    SmemMMA* sm = (SmemMMA*)smraw;
    const int nv = blockIdx.y, p = blockIdx.x;
    const int tid = threadIdx.x, lane = tid & 31, w = tid >> 5;
    const int gid = lane >> 2, t = lane & 3;
    u32 mbA = smem_u32(&sm->mbar[0]);

    if (tid == 0) {
        mbar_init(mbA, 1);
        mbar_expect_tx(mbA, 147456);
        const char* src = (const char*)(g_AloE + (size_t)nv * (NW * MT * KT9 * 32));
        bulk_copy(src,          sm->alo,                 73728, mbA);
        bulk_copy(src + 73728, (char*)sm->alo + 73728,   73728, mbA);
    }
    for (int i = tid; i < 8 * HBUF_W; i += 256) ((u32*)sm->hbuf)[i] = 0;
    for (int i = tid; i < 2048; i += 256) {
        int b = i & 15, tt = i >> 4;
        sm->xs[i] = X[((size_t)(p * BSUB + b) * LSEQ + tt) * NVAR + nv];
    }
    u32 ahi[MT * KT9 * 4];
    {
        const uint4* gA = g_AhiE + ((size_t)nv * NW + w) * (MT * KT9 * 32);
        #pragma unroll
        for (int f = 0; f < MT * KT9; f++) {
            uint4 v = gA[f * 32 + lane];
            ahi[f * 4] = v.x; ahi[f * 4 + 1] = v.y; ahi[f * 4 + 2] = v.z; ahi[f * 4 + 3] = v.w;
        }
    }
    __syncthreads();
    // bias rows (k130,k131 = 1.0) in hi buffers, all (g,par); x(0) into par0 buffers
    if (tid < 32) {
        int g = tid >> 4, par = (tid >> 3) & 1, row = tid & 7;
        sm->hbuf[(g << 2) | (par << 1)][row * HSTR + 65] = 0x3F803F80u;
    }
    if (tid < 16) {
        int g = tid >> 3, row = tid & 7;
        float x = sm->xs[tid];
        unsigned short xh = f2bf(x);
        unsigned short xl = f2bf(x - bf2f(xh));
        sm->hbuf[(g << 2)][row * HSTR + 64]     = (u32)xh | ((u32)xh << 16);
        sm->hbuf[(g << 2) | 1][row * HSTR + 64] = (u32)xl;
    }
    mbar_wait(mbA, 0);
    __syncthreads();

    const int u0 = 16 * w + gid, u1 = u0 + 8;
    const float pw0 = pool_w[nv * DD + u0], pw1 = pool_w[nv * DD + u1];
    const float pb = pool_b[nv];
    float cA[2][2], cB[2][2], hA[2][2], hB[2][2];
    float accCA[2][2], accCB[2][2], pmA[2], pmB[2], psA[2], psB[2];
    #pragma unroll
    for (int ui = 0; ui < 2; ui++)
        #pragma unroll
        for (int j = 0; j < 2; j++) {
            cA[ui][j] = cB[ui][j] = 0.f;
            accCA[ui][j] = accCB[ui][j] = 0.f;
        }
    #pragma unroll
    for (int j = 0; j < 2; j++) { pmA[j] = pmB[j] = -1e30f; psA[j] = psB[j] = 0.f; }

    const uint4* aloW = sm->alo + w * (MT * KT9 * 32);
    float accA[4][4], accB[4][4];
    #pragma unroll
    for (int m = 0; m < 4; m++)
        #pragma unroll
        for (int r = 0; r < 4; r++) accA[m][r] = 0.f;
    do_mma_g(aloW, sm->hbuf[0], ahi, accA, lane);      // GEMM_A(0), reads [g0][par0]

    const int TS = LSEQ - 1;
    for (int ts = 0; ts < TS; ts++) {
        int par = ts & 1;
        // ---- stage 1: GEMM_B(ts) ----
        #pragma unroll
        for (int m = 0; m < 4; m++)
            #pragma unroll
            for (int r = 0; r < 4; r++) accB[m][r] = 0.f;
        do_mma_g(aloW, sm->hbuf[4 | (par << 1)], ahi, accB, lane);
        // ---- stage 2: epilogue A(ts) ----
        gates_group(accA, cA, hA);
        u32 hibA = smem_u32(sm->hbuf[(par ^ 1) << 1]);
        store_group(hibA, hA, t, u0, u1);
        if (tid < 8 && ts + 1 < LSEQ) {
            float x = sm->xs[(ts + 1) * 16 + tid];
            unsigned short xh = f2bf(x);
            unsigned short xl = f2bf(x - bf2f(xh));
            sm->hbuf[(par ^ 1) << 1][tid * HSTR + 64]       = (u32)xh | ((u32)xh << 16);
            sm->hbuf[((par ^ 1) << 1) | 1][tid * HSTR + 64] = (u32)xl;
        }
        {
            float part[2];
            #pragma unroll
            for (int j = 0; j < 2; j++) part[j] = hA[0][j] * pw0 + hA[1][j] * pw1;
            #pragma unroll
            for (int off = 4; off <= 16; off <<= 1)
                #pragma unroll
                for (int j = 0; j < 2; j++)
                    part[j] += __shfl_xor_sync(0xffffffffu, part[j], off);
            if (gid == 0) { sm->sp[w][2 * t] = part[0]; sm->sp[w][2 * t + 1] = part[1]; }
        }
        __syncthreads();   // bar1: h_A(ts), x, sp(A) visible
        // ---- accC_A update ----
        #pragma unroll
        for (int j = 0; j < 2; j++) {
            float s = pb;
            #pragma unroll
            for (int ww = 0; ww < NW; ww++) s += sm->sp[ww][2 * t + j];
            float mn = fmaxf(pmA[j], s);
            float scale = __expf(pmA[j] - mn);
            float wcur  = __expf(s - mn);
            psA[j] = psA[j] * scale + wcur;
            pmA[j] = mn;
            accCA[0][j] = accCA[0][j] * scale + wcur * hA[0][j];
            accCA[1][j] = accCA[1][j] * scale + wcur * hA[1][j];
        }
        // ---- stage 4: GEMM_A(ts+1) ----
        if (ts + 1 < TS) {
            #pragma unroll
            for (int m = 0; m < 4; m++)
                #pragma unroll
                for (int r = 0; r < 4; r++) accA[m][r] = 0.f;
            do_mma_g(aloW, sm->hbuf[(par ^ 1) << 1], ahi, accA, lane);
        }
        // ---- stage 5: epilogue B(ts) ----
        gates_group(accB, cB, hB);
        u32 hibB = smem_u32(sm->hbuf[4 | ((par ^ 1) << 1)]);
        store_group(hibB, hB, t, u0, u1);
        if (tid >= 8 && tid < 16 && ts + 1 < LSEQ) {
            float x = sm->xs[(ts + 1) * 16 + tid];
            unsigned short xh = f2bf(x);
            unsigned short xl = f2bf(x - bf2f(xh));
            sm->hbuf[4 | ((par ^ 1) << 1)][(tid - 8) * HSTR + 64]       = (u32)xh | ((u32)xh << 16);
            sm->hbuf[4 | ((par ^ 1) << 1) | 1][(tid - 8) * HSTR + 64]   = (u32)xl;
        }
        {
            float part[2];
            #pragma unroll
            for (int j = 0; j < 2; j++) part[j] = hB[0][j] * pw0 + hB[1][j] * pw1;
            #pragma unroll
            for (int off = 4; off <= 16; off <<= 1)
                #pragma unroll
                for (int j = 0; j < 2; j++)
                    part[j] += __shfl_xor_sync(0xffffffffu, part[j], off);
            if (gid == 0) { sm->sp[w][8 + 2 * t] = part[0]; sm->sp[w][8 + 2 * t + 1] = part[1]; }
        }
        __syncthreads();   // bar2
        // ---- accC_B update ----
        #pragma unroll
        for (int j = 0; j < 2; j++) {
            float s = pb;
            #pragma unroll
            for (int ww = 0; ww < NW; ww++) s += sm->sp[ww][8 + 2 * t + j];
            float mn = fmaxf(pmB[j], s);
            float scale = __expf(pmB[j] - mn);
            float wcur  = __expf(s - mn);
            psB[j] = psB[j] * scale + wcur;
            pmB[j] = mn;
            accCB[0][j] = accCB[0][j] * scale + wcur * hB[0][j];
            accCB[1][j] = accCB[1][j] * scale + wcur * hB[1][j];
        }
    }
    #pragma unroll
    for (int j = 0; j < 2; j++) {
        int bA = p * BSUB + 2 * t + j;
        int bB = bA + 8;
        float ivA = __fdividef(1.f, psA[j]);
        float ivB = __fdividef(1.f, psB[j]);
        g_C[((size_t)bA * NVAR + nv) * DD + u0] = accCA[0][j] * ivA;
        g_C[((size_t)bA * NVAR + nv) * DD + u1] = accCA[1][j] * ivA;
        g_C[((size_t)bB * NVAR + nv) * DD + u0] = accCB[0][j] * ivB;
        g_C[((size_t)bB * NVAR + nv) * DD + u1] = accCB[1][j] * ivB;
    }
}

// ================= MHSA (unchanged) =================
__global__ __launch_bounds__(128, 1) void mhsa_kernel(
    const float* __restrict__ bqkv,
    const float* __restrict__ Wo, const float* __restrict__ bo,
    float* __restrict__ out) {
    extern __shared__ __align__(16) float smf[];
    float* Cs  = smf;
    float* QKV = smf + 4352;
    float* As  = smf;
    const int b = blockIdx.x, tid = threadIdx.x;

    #pragma unroll 4
    for (int i = 0; i < 32; i++)
        Cs[tid * 34 + i] = g_C[(b * NVAR + i) * DD + tid];
    __syncthreads();

    for (int jj = 0; jj < 3; jj++) {
        int j = jj * 128 + tid;
        float bj = bqkv[j];
        u64 acc[16];
        #pragma unroll
        for (int vp = 0; vp < 16; vp++) acc[vp] = pack2(bj, bj);
        #pragma unroll 2
        for (int k = 0; k < DD; k++) {
            float wv = g_WqkvT[k * 384 + j];
            u64 ww = pack2(wv, wv);
            const u64* crow = (const u64*)&Cs[k * 34];
            #pragma unroll
            for (int vp = 0; vp < 16; vp++) acc[vp] = ffma2(ww, crow[vp], acc[vp]);
        }
        #pragma unroll
        for (int vp = 0; vp < 16; vp++) {
            float a0, a1; unpack2(acc[vp], a0, a1);
            QKV[(2 * vp)     * 385 + j] = a0;
            QKV[(2 * vp + 1) * 385 + j] = a1;
        }
    }
    __syncthreads();
    {
        int h = tid >> 5, i = tid & 31;
        float q[32];
        #pragma unroll
        for (int d = 0; d < 32; d++) q[d] = QKV[i * 385 + h * 32 + d];
        float s[32];
        #pragma unroll
        for (int j = 0; j < 32; j++) {
            float a = 0.f;
            #pragma unroll
            for (int d = 0; d < 32; d++) a += q[d] * QKV[j * 385 + 128 + h * 32 + d];
            s[j] = a * 0.17677669529663687f;
        }
        float mx = s[0];
        #pragma unroll
        for (int j = 1; j < 32; j++) mx = fmaxf(mx, s[j]);
        float sum = 0.f;
        #pragma unroll
        for (int j = 0; j < 32; j++) { s[j] = __expf(s[j] - mx); sum += s[j]; }
        float inv = __fdividef(1.f, sum);
        float A[32];
        #pragma unroll
        for (int d = 0; d < 32; d++) A[d] = 0.f;
        #pragma unroll
        for (int j = 0; j < 32; j++) {
            float aj = s[j] * inv;
            #pragma unroll
            for (int d = 0; d < 32; d++) A[d] += aj * QKV[j * 385 + 256 + h * 32 + d];
        }
        #pragma unroll
        for (int d = 0; d < 32; d++) As[i * 129 + h * 32 + d] = A[d];
    }
    __syncthreads();
    {
        int v = tid & 31, uc = tid >> 5;
        for (int mm = 0; mm < 32; mm++) {
            int u = uc * 32 + mm;
            float a = bo[u];
            #pragma unroll 4
            for (int d = 0; d < DD; d++) a += As[v * 129 + d] * Wo[u * DD + d];
            g_Cstar[(b * NVAR + v) * DD + u] = a;
            out[CSTAR_OFF + (b * NVAR + v) * DD + u] = a;
        }
    }
}

// ================= decoder =================
__global__ __launch_bounds__(256, 1) void dec_kernel(
    const float* __restrict__ ihW, const float* __restrict__ ihB,
    const float* __restrict__ icW, const float* __restrict__ icB,
    const float* __restrict__ outW, const float* __restrict__ outB,
    float* __restrict__ out) {
    extern __shared__ __align__(16) char smraw[];
    SmemMMA* sm = (SmemMMA*)smraw;
    const int nv = blockIdx.y, p = blockIdx.x;
    const int tid = threadIdx.x, lane = tid & 31, w = tid >> 5;
    const int gid = lane >> 2, t = lane & 3;
    u32 mbA = smem_u32(&sm->mbar[0]);

    if (tid == 0) {
        mbar_init(mbA, 1);
        mbar_expect_tx(mbA, 147456);
        const char* src = (const char*)(g_AloD + (size_t)nv * (NW * MT * KT9 * 32));
        bulk_copy(src,          sm->alo,                73728, mbA);
        bulk_copy(src + 73728, (char*)sm->alo + 73728,  73728, mbA);
    }
    for (int i = tid; i < 8 * HBUF_W; i += 256) ((u32*)sm->hbuf)[i] = 0;
    for (int i = tid; i < 2048; i += 256) {
        int b = i & 15, k = i >> 4;
        sm->xs[i] = g_Cstar[((size_t)(p * BSUB + b) * NVAR + nv) * DD + k];
    }
    u32 ahi[MT * KT9 * 4];
    {
        const uint4* gA = g_AhiD + ((size_t)nv * NW + w) * (MT * KT9 * 32);
        #pragma unroll
        for (int f = 0; f < MT * KT9; f++) {
            uint4 v = gA[f * 32 + lane];
            ahi[f * 4] = v.x; ahi[f * 4 + 1] = v.y; ahi[f * 4 + 2] = v.z; ahi[f * 4 + 3] = v.w;
        }
    }
    __syncthreads();
    if (tid < 32) {
        int g = tid >> 4, par = (tid >> 3) & 1, row = tid & 7;
        sm->hbuf[(g << 2) | (par << 1)][row * HSTR + 65] = 0x3F803F80u;
    }

    const int u0 = 16 * w + gid, u1 = u0 + 8;
    int gcols[4] = {2 * t, 2 * t + 1, 8 + 2 * t, 8 + 2 * t + 1};

    // init matvecs: h0 = tanh(cs@ihW^T + ihB), c0 = tanh(cs@icW^T + icB)
    float cA[2][2], cB[2][2], hA[2][2], hB[2][2];
    {
        float ah0[4], ah1[4], ac0[4], ac1[4];
        float bh0 = ihB[nv * DD + u0], bh1 = ihB[nv * DD + u1];
        float bc0 = icB[nv * DD + u0], bc1 = icB[nv * DD + u1];
        #pragma unroll
        for (int j = 0; j < 4; j++) { ah0[j] = bh0; ah1[j] = bh1; ac0[j] = bc0; ac1[j] = bc1; }
        const float* wh0 = ihW + ((size_t)nv * DD + u0) * DD;
        const float* wh1 = ihW + ((size_t)nv * DD + u1) * DD;
        const float* wc0 = icW + ((size_t)nv * DD + u0) * DD;
        const float* wc1 = icW + ((size_t)nv * DD + u1) * DD;
        #pragma unroll 2
        for (int k = 0; k < DD; k++) {
            float a0 = wh0[k], a1 = wh1[k], b0 = wc0[k], b1 = wc1[k];
            #pragma unroll
            for (int j = 0; j < 4; j++) {
                float cv = sm->xs[k * 16 + gcols[j]];
                ah0[j] += a0 * cv; ah1[j] += a1 * cv;
                ac0[j] += b0 * cv; ac1[j] += b1 * cv;
            }
        }
        #pragma unroll
        for (int j = 0; j < 2; j++) {
            hA[0][j] = ftanhf(ah0[j]);     hA[1][j] = ftanhf(ah1[j]);
            cA[0][j] = ftanhf(ac0[j]);     cA[1][j] = ftanhf(ac1[j]);
            hB[0][j] = ftanhf(ah0[2 + j]); hB[1][j] = ftanhf(ah1[2 + j]);
            cB[0][j] = ftanhf(ac0[2 + j]); cB[1][j] = ftanhf(ac1[2 + j]);
        }
    }
    __syncthreads();   // done reading staged cs; hbuf zero/bias visible
    store_group(smem_u32(sm->hbuf[0]), hA, t, u0, u1);     // h_A(init) -> [g0][par0]
    store_group(smem_u32(sm->hbuf[4]), hB, t, u0, u1);     // h_B(init) -> [g1][par0]
    mbar_wait(mbA, 0);
    __syncthreads();

    const float wo0 = outW[nv * DD + u0], wo1 = outW[nv * DD + u1];
    const float ob = outB[nv];
    const uint4* aloW = sm->alo + w * (MT * KT9 * 32);
    const int b_row0 = p * BSUB;

    float accA[4][4], accB[4][4];
    #pragma unroll
    for (int m = 0; m < 4; m++)
        #pragma unroll
        for (int r = 0; r < 4; r++) accA[m][r] = 0.f;
    do_mma_g(aloW, sm->hbuf[0], ahi, accA, lane);          // GEMM_A(0)

    for (int l = 0; l < LSEQ; l++) {
        int par = l & 1;
        #pragma unroll
        for (int m = 0; m < 4; m++)
            #pragma unroll
            for (int r = 0; r < 4; r++) accB[m][r] = 0.f;
        do_mma_g(aloW, sm->hbuf[4 | (par << 1)], ahi, accB, lane);   // GEMM_B(l)

        gates_group(accA, cA, hA);
        store_group(smem_u32(sm->hbuf[(par ^ 1) << 1]), hA, t, u0, u1);
        {
            float part[2];
            #pragma unroll
            for (int j = 0; j < 2; j++) part[j] = hA[0][j] * wo0 + hA[1][j] * wo1;
            #pragma unroll
            for (int off = 4; off <= 16; off <<= 1)
                #pragma unroll
                for (int j = 0; j < 2; j++)
                    part[j] += __shfl_xor_sync(0xffffffffu, part[j], off);
            if (gid == 0) { sm->sp[w][2 * t] = part[0]; sm->sp[w][2 * t + 1] = part[1]; }
        }
        __syncthreads();   // bar1
        if (tid < 8) {
            float O = ob;
            #pragma unroll
            for (int ww = 0; ww < NW; ww++) O += sm->sp[ww][tid];
            int b = b_row0 + tid;
            if (l < LSEQ - 1) out[((size_t)b * (LSEQ - 1) + l) * NVAR + nv] = O;
            else              out[PRED_OFF + b * NVAR + nv] = O;
        }
        if (l + 1 < LSEQ) {
            #pragma unroll
            for (int m = 0; m < 4; m++)
                #pragma unroll
                for (int r = 0; r < 4; r++) accA[m][r] = 0.f;
            do_mma_g(aloW, sm->hbuf[(par ^ 1) << 1], ahi, accA, lane);  // GEMM_A(l+1)
        }
        gates_group(accB, cB, hB);
        store_group(smem_u32(sm->hbuf[4 | ((par ^ 1) << 1)]), hB, t, u0, u1);
        {
            float part[2];
            #pragma unroll
            for (int j = 0; j < 2; j++) part[j] = hB[0][j] * wo0 + hB[1][j] * wo1;
            #pragma unroll
            for (int off = 4; off <= 16; off <<= 1)
                #pragma unroll
                for (int j = 0; j < 2; j++)
                    part[j] += __shfl_xor_sync(0xffffffffu, part[j], off);
            if (gid == 0) { sm->sp[w][8 + 2 * t] = part[0]; sm->sp[w][8 + 2 * t + 1] = part[1]; }
        }
        __syncthreads();   // bar2
        if (tid >= 8 && tid < 16) {
            float O = ob;
            #pragma unroll
            for (int ww = 0; ww < NW; ww++) O += sm->sp[ww][tid];
            int b = b_row0 + tid;
            if (l < LSEQ - 1) out[((size_t)b * (LSEQ - 1) + l) * NVAR + nv] = O;
            else              out[PRED_OFF + b * NVAR + nv] = O;
        }
    }
}

// ---------------- launch ----------------
extern "C" void kernel_launch(void* const* d_in, const int* in_sizes, int n_in,
                              void* d_out, int out_size) {
    (void)in_sizes; (void)n_in; (void)out_size;
    const float* X        = (const float*)d_in[0];
    const float* enc_Wih  = (const float*)d_in[1];
    const float* enc_Whh  = (const float*)d_in[2];
    const float* enc_bih  = (const float*)d_in[3];
    const float* enc_bhh  = (const float*)d_in[4];
    const float* pool_w   = (const float*)d_in[5];
    const float* pool_b   = (const float*)d_in[6];
    const float* Wqkv     = (const float*)d_in[7];
    const float* bqkv     = (const float*)d_in[8];
    const float* Wo       = (const float*)d_in[9];
    const float* bo       = (const float*)d_in[10];
    const float* dec_ih_W = (const float*)d_in[11];
    const float* dec_ih_b = (const float*)d_in[12];
    const float* dec_ic_W = (const float*)d_in[13];
    const float* dec_ic_b = (const float*)d_in[14];
    const float* dec_Wih  = (const float*)d_in[15];
    const float* dec_Whh  = (const float*)d_in[16];
    const float* dec_bih  = (const float*)d_in[17];
    const float* dec_bhh  = (const float*)d_in[18];
    const float* dec_out_W= (const float*)d_in[19];
    const float* dec_out_b= (const float*)d_in[20];
    float* out = (float*)d_out;

    static int attr_set = 0;
    if (!attr_set) {
        cudaFuncSetAttribute(mhsa_kernel, cudaFuncAttributeMaxDynamicSharedMemorySize, 66688);
        cudaFuncSetAttribute(enc_kernel,  cudaFuncAttributeMaxDynamicSharedMemorySize, SMEM_MMA);
        cudaFuncSetAttribute(dec_kernel,  cudaFuncAttributeMaxDynamicSharedMemorySize, SMEM_MMA);
        attr_set = 1;
    }

    uint4 *pAhiE, *pAloE, *pAhiD, *pAloD; float* pWqkvT;
    cudaGetSymbolAddress((void**)&pAhiE, g_AhiE);
    cudaGetSymbolAddress((void**)&pAloE, g_AloE);
    cudaGetSymbolAddress((void**)&pAhiD, g_AhiD);
    cudaGetSymbolAddress((void**)&pAloD, g_AloD);
    cudaGetSymbolAddress((void**)&pWqkvT, g_WqkvT);

    pack_w<<<1152, 256>>>(enc_Whh, enc_Wih, enc_bih, enc_bhh, pAhiE, pAloE, 1);
    pack_w<<<1152, 256>>>(dec_Whh, dec_Wih, dec_bih, dec_bhh, pAhiD, pAloD, 0);
    transpose_kernel<<<dim3(4, 12, 1), dim3(32, 8)>>>(Wqkv, pWqkvT, 384, 128);

    enc_kernel<<<dim3(PSPLIT, NVAR), 256, SMEM_MMA>>>(X, pool_w, pool_b);
    mhsa_kernel<<<BATCH, 128, 66688>>>(bqkv, Wo, bo, out);
    dec_kernel<<<dim3(PSPLIT, NVAR), 256, SMEM_MMA>>>(dec_ih_W, dec_ih_b, dec_ic_W, dec_ic_b,
                                                      dec_out_W, dec_out_b, out);
}